// round 6
// baseline (speedup 1.0000x reference)
#include <cuda_runtime.h>
#include <math.h>

#define Nn 4096
#define Dd 384
#define Ee 131072
#define Hh 8
#define DHh 48
#define Ll 3

typedef unsigned long long ull;

// ---------------- packed f32x2 helpers ---------------------------------------
__device__ __forceinline__ ull pk2(float x, float y) {
    ull r; asm("mov.b64 %0, {%1, %2};" : "=l"(r) : "f"(x), "f"(y)); return r;
}
__device__ __forceinline__ float2 upk(ull v) {
    float2 r; asm("mov.b64 {%0, %1}, %2;" : "=f"(r.x), "=f"(r.y) : "l"(v)); return r;
}
__device__ __forceinline__ void fma2(ull& d, ull a, ull b) {
    asm("fma.rn.f32x2 %0, %1, %2, %0;" : "+l"(d) : "l"(a), "l"(b));
}
__device__ __forceinline__ void mul2(ull& d, ull a) {
    asm("mul.rn.f32x2 %0, %0, %1;" : "+l"(d) : "l"(a));
}
__device__ __forceinline__ void add2(ull& d, ull a) {
    asm("add.rn.f32x2 %0, %0, %1;" : "+l"(d) : "l"(a));
}

// ---------------- scratch (static device globals; no runtime alloc) ----------
__device__ __align__(16) float g_h[Nn * Dd];
__device__ __align__(16) float g_agg[Nn * Dd];
__device__ __align__(16) float g_hnew[Nn * Dd];
__device__ __align__(16) float g_qkv[Nn * 3 * Dd];
__device__ __align__(16) float g_o[Nn * Dd];
__device__ int   g_deg[Nn];
__device__ float g_degf[Nn];
__device__ int   g_rowptr[Nn + 1];
__device__ int   g_fillpos[Nn];
__device__ int   g_colidx[Ee];

// ---------------- CSR build --------------------------------------------------
__global__ void k_zero_deg() {
    int i = blockIdx.x * blockDim.x + threadIdx.x;
    if (i < Nn) g_deg[i] = 0;
}

__global__ void k_hist(const int* __restrict__ ei) {
    int e = blockIdx.x * blockDim.x + threadIdx.x;
    if (e < Ee) atomicAdd(&g_deg[ei[e]], 1);
}

__global__ void k_scan() {
    __shared__ int s[1024];
    int tid = threadIdx.x;
    int b = tid * 4;
    int v0 = g_deg[b], v1 = g_deg[b + 1], v2 = g_deg[b + 2], v3 = g_deg[b + 3];
    int p1 = v0 + v1, p2 = p1 + v2, p3 = p2 + v3;
    s[tid] = p3;
    __syncthreads();
    for (int off = 1; off < 1024; off <<= 1) {
        int t = (tid >= off) ? s[tid - off] : 0;
        __syncthreads();
        if (tid >= off) s[tid] += t;
        __syncthreads();
    }
    int prev = tid ? s[tid - 1] : 0;
    int e0 = prev, e1 = prev + v0, e2 = prev + p1, e3 = prev + p2;
    g_rowptr[b]     = e0; g_rowptr[b + 1] = e1;
    g_rowptr[b + 2] = e2; g_rowptr[b + 3] = e3;
    g_fillpos[b]     = e0; g_fillpos[b + 1] = e1;
    g_fillpos[b + 2] = e2; g_fillpos[b + 3] = e3;
    g_degf[b]     = (float)v0; g_degf[b + 1] = (float)v1;
    g_degf[b + 2] = (float)v2; g_degf[b + 3] = (float)v3;
    if (tid == 1023) g_rowptr[Nn] = s[1023];
}

__global__ void k_fill(const int* __restrict__ ei) {
    int e = blockIdx.x * blockDim.x + threadIdx.x;
    if (e < Ee) {
        int dst = ei[e];
        int src = ei[Ee + e];
        int pos = atomicAdd(&g_fillpos[dst], 1);
        g_colidx[pos] = src;
    }
}

__global__ void k_copy(const float* __restrict__ emb) {
    int i = blockIdx.x * blockDim.x + threadIdx.x;
    if (i < Nn * Dd / 4)
        ((float4*)g_h)[i] = ((const float4*)emb)[i];
}

// ---------------- neighbor aggregation (warp per node, deterministic) --------
__global__ __launch_bounds__(256) void k_gather() {
    int warp = (blockIdx.x * blockDim.x + threadIdx.x) >> 5;
    int lane = threadIdx.x & 31;
    if (warp >= Nn) return;
    int pbeg = g_rowptr[warp], pend = g_rowptr[warp + 1];
    ull a[6] = {0, 0, 0, 0, 0, 0};
    for (int p = pbeg; p < pend; p++) {
        int src = g_colidx[p];
        const ulonglong2* r = (const ulonglong2*)(g_h + src * Dd);
        ulonglong2 x;
        x = r[lane];      add2(a[0], x.x); add2(a[1], x.y);
        x = r[lane + 32]; add2(a[2], x.x); add2(a[3], x.y);
        x = r[lane + 64]; add2(a[4], x.x); add2(a[5], x.y);
    }
    ulonglong2* w = (ulonglong2*)(g_agg + warp * Dd);
    ulonglong2 o;
    o.x = a[0]; o.y = a[1]; w[lane]      = o;
    o.x = a[2]; o.y = a[3]; w[lane + 32] = o;
    o.x = a[4]; o.y = a[5]; w[lane + 64] = o;
}

// ---------------- GEMM: C[m][n] = sum_k A[m][k]*B[n][k] + epilogue -----------
// MODE 0: A=g_agg  -> C=g_hnew, bias scaled by per-row degree        (conv)
// MODE 1: A=g_hnew -> C=g_qkv,  plain bias, Nout=3D                  (qkv)
// MODE 2: A=g_o    -> C=g_h,    bias + residual g_h, relu, in-place  (attn out)
template <int MODE>
__global__ __launch_bounds__(256) void k_gemm(const float* __restrict__ B,
                                              const float* __restrict__ bias) {
    const float* A;
    float* C;
    int Nout;
    if (MODE == 0)      { A = g_agg;  C = g_hnew; Nout = Dd; }
    else if (MODE == 1) { A = g_hnew; C = g_qkv;  Nout = 3 * Dd; }
    else                { A = g_o;    C = g_h;    Nout = Dd; }

    // As2: A tile duplicated along cols so broadcast operand is LDS.64-packed
    __shared__ __align__(16) float As2[32 * 136];   // [k][2m],[2m+1]
    __shared__ __align__(16) float Bs[32 * 68];
    int tid = threadIdx.x;
    int tx = tid & 15, ty = tid >> 4;
    int row0 = blockIdx.y * 64, col0 = blockIdx.x * 64;

    ull acc[4][2];
#pragma unroll
    for (int i = 0; i < 4; i++) { acc[i][0] = 0ull; acc[i][1] = 0ull; }

    for (int k0 = 0; k0 < Dd; k0 += 32) {
#pragma unroll
        for (int i = tid; i < 64 * 32; i += 256) {
            int m = i >> 5, k = i & 31;
            float v = A[(row0 + m) * Dd + k0 + k];
            ((float2*)&As2[k * 136 + 2 * m])[0] = make_float2(v, v);
        }
#pragma unroll
        for (int i = tid; i < 64 * 32; i += 256) {
            int n = i >> 5, k = i & 31;
            Bs[k * 68 + n] = B[(col0 + n) * Dd + k0 + k];
        }
        __syncthreads();
#pragma unroll 8
        for (int kk = 0; kk < 32; kk++) {
            const ull* ar = (const ull*)&As2[kk * 136];
            ulonglong2 b = *(const ulonglong2*)&Bs[kk * 68 + tx * 4];
            ull a0 = ar[ty * 4 + 0];
            ull a1 = ar[ty * 4 + 1];
            ull a2 = ar[ty * 4 + 2];
            ull a3 = ar[ty * 4 + 3];
            fma2(acc[0][0], a0, b.x); fma2(acc[0][1], a0, b.y);
            fma2(acc[1][0], a1, b.x); fma2(acc[1][1], a1, b.y);
            fma2(acc[2][0], a2, b.x); fma2(acc[2][1], a2, b.y);
            fma2(acc[3][0], a3, b.x); fma2(acc[3][1], a3, b.y);
        }
        __syncthreads();
    }

#pragma unroll
    for (int i = 0; i < 4; i++) {
        int m = row0 + ty * 4 + i;
        float rmul = (MODE == 0) ? g_degf[m] : 1.0f;
        float2 c01 = upk(acc[i][0]);
        float2 c23 = upk(acc[i][1]);
        float cv[4] = {c01.x, c01.y, c23.x, c23.y};
#pragma unroll
        for (int j = 0; j < 4; j++) {
            int n = col0 + tx * 4 + j;
            float v = cv[j] + bias[n] * rmul;
            if (MODE == 2) {
                v += g_h[m * Dd + n];
                v = fmaxf(v, 0.f);
            }
            C[m * Nout + n] = v;
        }
    }
}

// ---------------- flash attention: per (head, 128-query tile), 512 thr -------
// smem layout (floats):
//  Qs2 [48][264]  (duplicated along 2m)     : 12672
//  Ks  [48][64]                             :  3072
//  Vs  [64][48]                             :  3072
//  Ps  [64][132]  transposed + xor-swizzled :  8448
#define QS2_OFF 0
#define KS_OFF  12672
#define VS_OFF  15744
#define PS_OFF  18816
#define FLASH_SMEM_FLOATS 27264

__global__ __launch_bounds__(512, 2) void k_flash() {
    extern __shared__ __align__(16) float sm[];
    float* Qs2 = sm + QS2_OFF;
    float* Ks  = sm + KS_OFF;
    float* Vs  = sm + VS_OFF;
    float* Ps  = sm + PS_OFF;
    int head = blockIdx.y;
    int q0 = blockIdx.x * 128;
    int tid = threadIdx.x, tx = tid & 15, ty = tid >> 4;   // ty: 0..31
    const float scale = 0.14433756729740643f;  // 1/sqrt(48)

    // load + duplicate Q tile (128 rows x 48 dims), scale folded in
    for (int i = tid; i < 128 * 48; i += 512) {
        int m = i / 48, d = i - m * 48;
        float v = g_qkv[(q0 + m) * 1152 + head * 48 + d] * scale;
        ((float2*)&Qs2[d * 264 + 2 * m])[0] = make_float2(v, v);
    }

    float mr[4], lr[4];
    ull Op[2][3];       // row-pairs (ty*4+0,1) / (ty*4+2,3)  x 3 cols
#pragma unroll
    for (int i = 0; i < 4; i++) { mr[i] = -1e30f; lr[i] = 0.f; }
#pragma unroll
    for (int p = 0; p < 2; p++)
#pragma unroll
        for (int c = 0; c < 3; c++) Op[p][c] = 0ull;
    __syncthreads();

    for (int k0 = 0; k0 < Nn; k0 += 64) {
        for (int i = tid; i < 64 * 48; i += 512) {
            int n = i / 48, d = i - n * 48;
            Ks[d * 64 + n] = g_qkv[(k0 + n) * 1152 + 384 + head * 48 + d];
        }
        for (int i = tid; i < 64 * 48; i += 512) {
            int n = i / 48, d = i - n * 48;
            Vs[n * 48 + d] = g_qkv[(k0 + n) * 1152 + 768 + head * 48 + d];
        }
        __syncthreads();

        // S = Q K^T  (packed along cols)
        ull sp[4][2];
#pragma unroll
        for (int i = 0; i < 4; i++) { sp[i][0] = 0ull; sp[i][1] = 0ull; }
#pragma unroll 8
        for (int kk = 0; kk < 48; kk++) {
            const ull* ar = (const ull*)&Qs2[kk * 264];
            ulonglong2 b = *(const ulonglong2*)&Ks[kk * 64 + tx * 4];
            ull a0 = ar[ty * 4 + 0];
            ull a1 = ar[ty * 4 + 1];
            ull a2 = ar[ty * 4 + 2];
            ull a3 = ar[ty * 4 + 3];
            fma2(sp[0][0], a0, b.x); fma2(sp[0][1], a0, b.y);
            fma2(sp[1][0], a1, b.x); fma2(sp[1][1], a1, b.y);
            fma2(sp[2][0], a2, b.x); fma2(sp[2][1], a2, b.y);
            fma2(sp[3][0], a3, b.x); fma2(sp[3][1], a3, b.y);
        }

        float s[4][4];
#pragma unroll
        for (int i = 0; i < 4; i++) {
            float2 s01 = upk(sp[i][0]);
            float2 s23 = upk(sp[i][1]);
            s[i][0] = s01.x; s[i][1] = s01.y; s[i][2] = s23.x; s[i][3] = s23.y;
        }

        // online softmax (row stats over the 16 tx threads of this half-warp)
        float alpha[4];
#pragma unroll
        for (int i = 0; i < 4; i++) {
            float vmax = fmaxf(fmaxf(s[i][0], s[i][1]), fmaxf(s[i][2], s[i][3]));
#pragma unroll
            for (int off = 8; off; off >>= 1)
                vmax = fmaxf(vmax, __shfl_xor_sync(0xffffffffu, vmax, off));
            float nm = fmaxf(mr[i], vmax);
            float sum = 0.f;
#pragma unroll
            for (int j = 0; j < 4; j++) {
                s[i][j] = __expf(s[i][j] - nm);
                sum += s[i][j];
            }
#pragma unroll
            for (int off = 8; off; off >>= 1)
                sum += __shfl_xor_sync(0xffffffffu, sum, off);
            alpha[i] = __expf(mr[i] - nm);
            lr[i] = lr[i] * alpha[i] + sum;
            mr[i] = nm;
        }
        {
            ull a01 = pk2(alpha[0], alpha[1]);
            ull a23 = pk2(alpha[2], alpha[3]);
#pragma unroll
            for (int c = 0; c < 3; c++) { mul2(Op[0][c], a01); mul2(Op[1][c], a23); }
        }

        // store P transposed [col][row] with xor swizzle on 4-row groups
        {
            int sw = tx & 7;
            int rbase = ((ty ^ sw) << 2);
#pragma unroll
            for (int j = 0; j < 4; j++) {
                int col = tx * 4 + j;
#pragma unroll
                for (int i = 0; i < 4; i++)
                    Ps[col * 132 + rbase + i] = s[i][j];
            }
        }
        __syncthreads();

        // O += P V   (P row-pairs pre-packed from LDS.128; V via scalar LDS —
        // 3*tx is only 4B-aligned, so no vector load here)
        int c0 = tx * 3;
#pragma unroll 4
        for (int j = 0; j < 64; j++) {
            int rb = ((ty ^ ((j >> 2) & 7)) << 2);
            ulonglong2 pq = *(const ulonglong2*)&Ps[j * 132 + rb];
            float v0s = Vs[j * 48 + c0];
            float v1s = Vs[j * 48 + c0 + 1];
            float v2s = Vs[j * 48 + c0 + 2];
            ull vb0 = pk2(v0s, v0s);
            ull vb1 = pk2(v1s, v1s);
            ull vb2 = pk2(v2s, v2s);
            fma2(Op[0][0], pq.x, vb0); fma2(Op[1][0], pq.y, vb0);
            fma2(Op[0][1], pq.x, vb1); fma2(Op[1][1], pq.y, vb1);
            fma2(Op[0][2], pq.x, vb2); fma2(Op[1][2], pq.y, vb2);
        }
        __syncthreads();
    }

    // epilogue: normalize + scatter to g_o
#pragma unroll
    for (int p = 0; p < 2; p++) {
        float inv0 = 1.f / lr[p * 2 + 0];
        float inv1 = 1.f / lr[p * 2 + 1];
        int r0 = q0 + ty * 4 + p * 2;
#pragma unroll
        for (int c = 0; c < 3; c++) {
            float2 o = upk(Op[p][c]);
            g_o[(r0 + 0) * 384 + head * 48 + tx * 3 + c] = o.x * inv0;
            g_o[(r0 + 1) * 384 + head * 48 + tx * 3 + c] = o.y * inv1;
        }
    }
}

// ---------------- output projection + sigmoid --------------------------------
__global__ __launch_bounds__(256) void k_out(const float* __restrict__ Wout,
                                             const float* __restrict__ bout,
                                             float* __restrict__ out) {
    int warp = (blockIdx.x * blockDim.x + threadIdx.x) >> 5;
    int lane = threadIdx.x & 31;
    if (warp >= Nn) return;
    const float4* hr = (const float4*)(g_h + warp * Dd);
    const float4* wr = (const float4*)Wout;
    float s = 0.f;
#pragma unroll
    for (int q = 0; q < 3; q++) {
        float4 a = hr[lane + 32 * q];
        float4 b = wr[lane + 32 * q];
        s += a.x * b.x + a.y * b.y + a.z * b.z + a.w * b.w;
    }
#pragma unroll
    for (int off = 16; off; off >>= 1)
        s += __shfl_xor_sync(0xffffffffu, s, off);
    if (lane == 0) out[warp] = 1.f / (1.f + __expf(-(s + bout[0])));
}

// ---------------- launch ------------------------------------------------------
extern "C" void kernel_launch(void* const* d_in, const int* in_sizes, int n_in,
                              void* d_out, int out_size) {
    const float* emb  = (const float*)d_in[0];
    const int*   ei   = (const int*)d_in[1];
    const float* Wc   = (const float*)d_in[2];
    const float* bc   = (const float*)d_in[3];
    const float* Win  = (const float*)d_in[4];
    const float* bin  = (const float*)d_in[5];
    const float* Wao  = (const float*)d_in[6];
    const float* bao  = (const float*)d_in[7];
    const float* Wout = (const float*)d_in[8];
    const float* bout = (const float*)d_in[9];
    float* out = (float*)d_out;

    cudaFuncSetAttribute(k_flash, cudaFuncAttributeMaxDynamicSharedMemorySize,
                         FLASH_SMEM_FLOATS * 4);

    // CSR build (reused across all 3 layers)
    k_zero_deg<<<Nn / 256, 256>>>();
    k_hist<<<Ee / 256, 256>>>(ei);
    k_scan<<<1, 1024>>>();
    k_fill<<<Ee / 256, 256>>>(ei);
    k_copy<<<(Nn * Dd / 4) / 256, 256>>>(emb);

    for (int l = 0; l < Ll; l++) {
        k_gather<<<Nn / 8, 256>>>();
        k_gemm<0><<<dim3(Dd / 64, Nn / 64), 256>>>(Wc + l * Dd * Dd, bc + l * Dd);
        k_gemm<1><<<dim3(3 * Dd / 64, Nn / 64), 256>>>(Win, bin);
        k_flash<<<dim3(Nn / 128, Hh), 512, FLASH_SMEM_FLOATS * 4>>>();
        k_gemm<2><<<dim3(Dd / 64, Nn / 64), 256>>>(Wao, bao);
    }
    k_out<<<Nn / 8, 256>>>(Wout, bout, out);
}

// round 7
// speedup vs baseline: 2.0979x; 2.0979x over previous
#include <cuda_runtime.h>
#include <math.h>

#define Nn 4096
#define Dd 384
#define Ee 131072
#define Hh 8
#define DHh 48
#define Ll 3

// ---------------- scratch (static device globals; no runtime alloc) ----------
__device__ __align__(16) float g_h[Nn * Dd];
__device__ __align__(16) float g_agg[Nn * Dd];
__device__ __align__(16) float g_hnew[Nn * Dd];
__device__ __align__(16) float g_qkv[Nn * 3 * Dd];
__device__ __align__(16) float g_o[Nn * Dd];
__device__ int   g_deg[Nn];
__device__ float g_degf[Nn];
__device__ int   g_rowptr[Nn + 1];
__device__ int   g_fillpos[Nn];
__device__ int   g_colidx[Ee];

// ---------------- CSR build --------------------------------------------------
__global__ void k_zero_deg() {
    int i = blockIdx.x * blockDim.x + threadIdx.x;
    if (i < Nn) g_deg[i] = 0;
}

__global__ void k_hist(const int* __restrict__ ei) {
    int e = blockIdx.x * blockDim.x + threadIdx.x;
    if (e < Ee) atomicAdd(&g_deg[ei[e]], 1);
}

__global__ void k_scan() {
    __shared__ int s[1024];
    int tid = threadIdx.x;
    int b = tid * 4;
    int v0 = g_deg[b], v1 = g_deg[b + 1], v2 = g_deg[b + 2], v3 = g_deg[b + 3];
    int p1 = v0 + v1, p2 = p1 + v2, p3 = p2 + v3;
    s[tid] = p3;
    __syncthreads();
    for (int off = 1; off < 1024; off <<= 1) {
        int t = (tid >= off) ? s[tid - off] : 0;
        __syncthreads();
        if (tid >= off) s[tid] += t;
        __syncthreads();
    }
    int prev = tid ? s[tid - 1] : 0;
    int e0 = prev, e1 = prev + v0, e2 = prev + p1, e3 = prev + p2;
    g_rowptr[b]     = e0; g_rowptr[b + 1] = e1;
    g_rowptr[b + 2] = e2; g_rowptr[b + 3] = e3;
    g_fillpos[b]     = e0; g_fillpos[b + 1] = e1;
    g_fillpos[b + 2] = e2; g_fillpos[b + 3] = e3;
    g_degf[b]     = (float)v0; g_degf[b + 1] = (float)v1;
    g_degf[b + 2] = (float)v2; g_degf[b + 3] = (float)v3;
    if (tid == 1023) g_rowptr[Nn] = s[1023];
}

__global__ void k_fill(const int* __restrict__ ei) {
    int e = blockIdx.x * blockDim.x + threadIdx.x;
    if (e < Ee) {
        int dst = ei[e];
        int src = ei[Ee + e];
        int pos = atomicAdd(&g_fillpos[dst], 1);
        g_colidx[pos] = src;
    }
}

__global__ void k_copy(const float* __restrict__ emb) {
    int i = blockIdx.x * blockDim.x + threadIdx.x;
    if (i < Nn * Dd / 4)
        ((float4*)g_h)[i] = ((const float4*)emb)[i];
}

// ---------------- neighbor aggregation (warp per node, deterministic) --------
__global__ __launch_bounds__(256) void k_gather() {
    int warp = (blockIdx.x * blockDim.x + threadIdx.x) >> 5;
    int lane = threadIdx.x & 31;
    if (warp >= Nn) return;
    int pbeg = g_rowptr[warp], pend = g_rowptr[warp + 1];
    float4 a0 = {0, 0, 0, 0}, a1 = a0, a2 = a0;
    for (int p = pbeg; p < pend; p++) {
        int src = g_colidx[p];
        const float4* r = (const float4*)(g_h + src * Dd);
        float4 x;
        x = r[lane];      a0.x += x.x; a0.y += x.y; a0.z += x.z; a0.w += x.w;
        x = r[lane + 32]; a1.x += x.x; a1.y += x.y; a1.z += x.z; a1.w += x.w;
        x = r[lane + 64]; a2.x += x.x; a2.y += x.y; a2.z += x.z; a2.w += x.w;
    }
    float4* w = (float4*)(g_agg + warp * Dd);
    w[lane] = a0; w[lane + 32] = a1; w[lane + 64] = a2;
}

// ---------------- GEMM: C[m][n] = sum_k A[m][k]*B[n][k] + epilogue -----------
// 128x64 C-tile, 256 threads, 8x4 micro-tile.
// MODE 0: A=g_agg  -> C=g_hnew, bias scaled by per-row degree        (conv)
// MODE 1: A=g_hnew -> C=g_qkv,  plain bias, Nout=3D                  (qkv)
// MODE 2: A=g_o    -> C=g_h,    bias + residual g_h, relu, in-place  (attn out)
template <int MODE>
__global__ __launch_bounds__(256, 2) void k_gemm(const float* __restrict__ B,
                                                 const float* __restrict__ bias) {
    const float* A;
    float* C;
    int Nout;
    if (MODE == 0)      { A = g_agg;  C = g_hnew; Nout = Dd; }
    else if (MODE == 1) { A = g_hnew; C = g_qkv;  Nout = 3 * Dd; }
    else                { A = g_o;    C = g_h;    Nout = Dd; }

    __shared__ __align__(16) float As[32 * 132];   // [k][m], m-stride 132
    __shared__ __align__(16) float Bs[32 * 68];    // [k][n], n-stride 68
    int tid = threadIdx.x;
    int tx = tid & 15, ty = tid >> 4;
    int row0 = blockIdx.y * 128, col0 = blockIdx.x * 64;

    float acc[8][4];
#pragma unroll
    for (int i = 0; i < 8; i++)
#pragma unroll
        for (int j = 0; j < 4; j++) acc[i][j] = 0.f;

    for (int k0 = 0; k0 < Dd; k0 += 32) {
        // A tile 128x32: per thread 4 x (LDG.128 + 4 scalar transposed STS)
#pragma unroll
        for (int i = tid; i < 1024; i += 256) {
            int m = i & 127, k4 = (i >> 7) * 4;
            float4 a = *(const float4*)&A[(row0 + m) * Dd + k0 + k4];
            As[(k4 + 0) * 132 + m] = a.x;
            As[(k4 + 1) * 132 + m] = a.y;
            As[(k4 + 2) * 132 + m] = a.z;
            As[(k4 + 3) * 132 + m] = a.w;
        }
        // B tile 64x32
#pragma unroll
        for (int i = tid; i < 512; i += 256) {
            int n = i & 63, k4 = (i >> 6) * 4;
            float4 b = *(const float4*)&B[(col0 + n) * Dd + k0 + k4];
            Bs[(k4 + 0) * 68 + n] = b.x;
            Bs[(k4 + 1) * 68 + n] = b.y;
            Bs[(k4 + 2) * 68 + n] = b.z;
            Bs[(k4 + 3) * 68 + n] = b.w;
        }
        __syncthreads();
#pragma unroll 8
        for (int kk = 0; kk < 32; kk++) {
            float4 a0 = *(const float4*)&As[kk * 132 + ty * 8];
            float4 a1 = *(const float4*)&As[kk * 132 + ty * 8 + 4];
            float4 b  = *(const float4*)&Bs[kk * 68 + tx * 4];
            float av[8] = {a0.x, a0.y, a0.z, a0.w, a1.x, a1.y, a1.z, a1.w};
            float bv[4] = {b.x, b.y, b.z, b.w};
#pragma unroll
            for (int i = 0; i < 8; i++)
#pragma unroll
                for (int j = 0; j < 4; j++) acc[i][j] += av[i] * bv[j];
        }
        __syncthreads();
    }

#pragma unroll
    for (int i = 0; i < 8; i++) {
        int m = row0 + ty * 8 + i;
        float rmul = (MODE == 0) ? g_degf[m] : 1.0f;
#pragma unroll
        for (int j = 0; j < 4; j++) {
            int n = col0 + tx * 4 + j;
            float v = acc[i][j] + bias[n] * rmul;
            if (MODE == 2) {
                v += g_h[m * Dd + n];
                v = fmaxf(v, 0.f);
            }
            C[m * Nout + n] = v;
        }
    }
}

// ---------------- flash attention: per (head, 128-query tile), 256 thr -------
// smem (floats): Qs[48][128]=6144, Ks[48][64]=3072, Vs[64][48]=3072,
//                Ps[128][68]=8704  -> total 20992 floats = 83968 B (2 blk/SM)
#define QS_OFF 0
#define KS_OFF 6144
#define VS_OFF 9216
#define PS_OFF 12288
#define FLASH_SMEM_FLOATS 20992

__global__ __launch_bounds__(256, 2) void k_flash() {
    extern __shared__ __align__(16) float sm[];
    float* Qs = sm + QS_OFF;
    float* Ks = sm + KS_OFF;
    float* Vs = sm + VS_OFF;
    float* Ps = sm + PS_OFF;
    int head = blockIdx.y;
    int q0 = blockIdx.x * 128;
    int tid = threadIdx.x, tx = tid & 15, ty = tid >> 4;
    const float scale = 0.14433756729740643f;  // 1/sqrt(48)

    // load Q tile (128 rows x 48 dims) transposed to [d][m], scale folded in
#pragma unroll
    for (int i = tid; i < 128 * 12; i += 256) {
        int m = i / 12, d4 = (i % 12) * 4;
        float4 q = *(const float4*)&g_qkv[(q0 + m) * 1152 + head * 48 + d4];
        Qs[(d4 + 0) * 128 + m] = q.x * scale;
        Qs[(d4 + 1) * 128 + m] = q.y * scale;
        Qs[(d4 + 2) * 128 + m] = q.z * scale;
        Qs[(d4 + 3) * 128 + m] = q.w * scale;
    }

    float mr[8], lr[8], O[8][3];
#pragma unroll
    for (int i = 0; i < 8; i++) {
        mr[i] = -1e30f; lr[i] = 0.f;
        O[i][0] = O[i][1] = O[i][2] = 0.f;
    }

    for (int k0 = 0; k0 < Nn; k0 += 64) {
        __syncthreads();   // guard Vs/Ps reuse from previous iteration
#pragma unroll
        for (int i = tid; i < 64 * 12; i += 256) {
            int n = i / 12, d4 = (i % 12) * 4;
            float4 k = *(const float4*)&g_qkv[(k0 + n) * 1152 + 384 + head * 48 + d4];
            Ks[(d4 + 0) * 64 + n] = k.x;
            Ks[(d4 + 1) * 64 + n] = k.y;
            Ks[(d4 + 2) * 64 + n] = k.z;
            Ks[(d4 + 3) * 64 + n] = k.w;
        }
#pragma unroll
        for (int i = tid; i < 64 * 12; i += 256) {
            int n = i / 12, d4 = (i % 12) * 4;
            *(float4*)&Vs[n * 48 + d4] =
                *(const float4*)&g_qkv[(k0 + n) * 1152 + 768 + head * 48 + d4];
        }
        __syncthreads();

        // S = Q K^T : 8x4 micro-tile
        float acc[8][4];
#pragma unroll
        for (int i = 0; i < 8; i++)
#pragma unroll
            for (int j = 0; j < 4; j++) acc[i][j] = 0.f;
#pragma unroll 8
        for (int kk = 0; kk < 48; kk++) {
            float4 a0 = *(const float4*)&Qs[kk * 128 + ty * 8];
            float4 a1 = *(const float4*)&Qs[kk * 128 + ty * 8 + 4];
            float4 b  = *(const float4*)&Ks[kk * 64 + tx * 4];
            float av[8] = {a0.x, a0.y, a0.z, a0.w, a1.x, a1.y, a1.z, a1.w};
            float bv[4] = {b.x, b.y, b.z, b.w};
#pragma unroll
            for (int i = 0; i < 8; i++)
#pragma unroll
                for (int j = 0; j < 4; j++) acc[i][j] += av[i] * bv[j];
        }

        // online softmax per row + P store (row group = 16 tx lanes, same warp)
#pragma unroll
        for (int i = 0; i < 8; i++) {
            float vmax = fmaxf(fmaxf(acc[i][0], acc[i][1]),
                               fmaxf(acc[i][2], acc[i][3]));
#pragma unroll
            for (int off = 8; off; off >>= 1)
                vmax = fmaxf(vmax, __shfl_xor_sync(0xffffffffu, vmax, off));
            float nm = fmaxf(mr[i], vmax);
            float sum = 0.f;
#pragma unroll
            for (int j = 0; j < 4; j++) {
                acc[i][j] = __expf(acc[i][j] - nm);
                sum += acc[i][j];
            }
#pragma unroll
            for (int off = 8; off; off >>= 1)
                sum += __shfl_xor_sync(0xffffffffu, sum, off);
            float alpha = __expf(mr[i] - nm);
            lr[i] = lr[i] * alpha + sum;
            mr[i] = nm;
            O[i][0] *= alpha; O[i][1] *= alpha; O[i][2] *= alpha;
            *(float4*)&Ps[(ty * 8 + i) * 68 + tx * 4] =
                make_float4(acc[i][0], acc[i][1], acc[i][2], acc[i][3]);
        }
        __syncwarp();   // P rows for this ty live in this warp only

        // O += P V : chunked over 4 keys, float4 P-row loads, scalar V bcast
        int c0 = tx * 3;
#pragma unroll 2
        for (int j0 = 0; j0 < 64; j0 += 4) {
            float4 p[8];
#pragma unroll
            for (int i = 0; i < 8; i++)
                p[i] = *(const float4*)&Ps[(ty * 8 + i) * 68 + j0];
#pragma unroll
            for (int jj = 0; jj < 4; jj++) {
                const float* vr = &Vs[(j0 + jj) * 48 + c0];
                float v0 = vr[0], v1 = vr[1], v2 = vr[2];
#pragma unroll
                for (int i = 0; i < 8; i++) {
                    float pij = (jj == 0) ? p[i].x : (jj == 1) ? p[i].y
                              : (jj == 2) ? p[i].z : p[i].w;
                    O[i][0] += pij * v0;
                    O[i][1] += pij * v1;
                    O[i][2] += pij * v2;
                }
            }
        }
    }

    // epilogue: normalize + scatter
#pragma unroll
    for (int i = 0; i < 8; i++) {
        float inv = 1.f / lr[i];
        int row = q0 + ty * 8 + i;
        g_o[row * 384 + head * 48 + tx * 3 + 0] = O[i][0] * inv;
        g_o[row * 384 + head * 48 + tx * 3 + 1] = O[i][1] * inv;
        g_o[row * 384 + head * 48 + tx * 3 + 2] = O[i][2] * inv;
    }
}

// ---------------- output projection + sigmoid --------------------------------
__global__ __launch_bounds__(256) void k_out(const float* __restrict__ Wout,
                                             const float* __restrict__ bout,
                                             float* __restrict__ out) {
    int warp = (blockIdx.x * blockDim.x + threadIdx.x) >> 5;
    int lane = threadIdx.x & 31;
    if (warp >= Nn) return;
    const float4* hr = (const float4*)(g_h + warp * Dd);
    const float4* wr = (const float4*)Wout;
    float s = 0.f;
#pragma unroll
    for (int q = 0; q < 3; q++) {
        float4 a = hr[lane + 32 * q];
        float4 b = wr[lane + 32 * q];
        s += a.x * b.x + a.y * b.y + a.z * b.z + a.w * b.w;
    }
#pragma unroll
    for (int off = 16; off; off >>= 1)
        s += __shfl_xor_sync(0xffffffffu, s, off);
    if (lane == 0) out[warp] = 1.f / (1.f + __expf(-(s + bout[0])));
}

// ---------------- launch ------------------------------------------------------
extern "C" void kernel_launch(void* const* d_in, const int* in_sizes, int n_in,
                              void* d_out, int out_size) {
    const float* emb  = (const float*)d_in[0];
    const int*   ei   = (const int*)d_in[1];
    const float* Wc   = (const float*)d_in[2];
    const float* bc   = (const float*)d_in[3];
    const float* Win  = (const float*)d_in[4];
    const float* bin  = (const float*)d_in[5];
    const float* Wao  = (const float*)d_in[6];
    const float* bao  = (const float*)d_in[7];
    const float* Wout = (const float*)d_in[8];
    const float* bout = (const float*)d_in[9];
    float* out = (float*)d_out;

    cudaFuncSetAttribute(k_flash, cudaFuncAttributeMaxDynamicSharedMemorySize,
                         FLASH_SMEM_FLOATS * 4);

    // CSR build (reused across all 3 layers)
    k_zero_deg<<<Nn / 256, 256>>>();
    k_hist<<<Ee / 256, 256>>>(ei);
    k_scan<<<1, 1024>>>();
    k_fill<<<Ee / 256, 256>>>(ei);
    k_copy<<<(Nn * Dd / 4) / 256, 256>>>(emb);

    for (int l = 0; l < Ll; l++) {
        k_gather<<<Nn / 8, 256>>>();
        k_gemm<0><<<dim3(Dd / 64, Nn / 128), 256>>>(Wc + l * Dd * Dd, bc + l * Dd);
        k_gemm<1><<<dim3(3 * Dd / 64, Nn / 128), 256>>>(Win, bin);
        k_flash<<<dim3(Nn / 128, Hh), 256, FLASH_SMEM_FLOATS * 4>>>();
        k_gemm<2><<<dim3(Dd / 64, Nn / 128), 256>>>(Wao, bao);
    }
    k_out<<<Nn / 8, 256>>>(Wout, bout, out);
}

// round 8
// speedup vs baseline: 2.1170x; 1.0091x over previous
#include <cuda_runtime.h>
#include <math.h>

#define Nn 4096
#define Dd 384
#define Ee 131072
#define Hh 8
#define DHh 48
#define Ll 3

// ---------------- fast exp2 on the FMA pipe (no MUFU) ------------------------
// Input domain: t <= ~0 (softmax exponents). Clamps at -126 (result ~0).
// Accuracy ~1e-7 relative. ~9 fma-pipe + 3 alu-pipe ops.
__device__ __forceinline__ float fexp2(float t) {
    t = fmaxf(t, -126.0f);
    float r = t + 12582912.0f;                 // round-to-nearest-int via magic
    int n = __float_as_int(r) - 0x4B400000;    // integer part
    float f = t - (r - 12582912.0f);           // f in [-0.5, 0.5]
    float p = 1.8775767e-3f;
    p = fmaf(p, f, 8.9893397e-3f);
    p = fmaf(p, f, 5.5826318e-2f);
    p = fmaf(p, f, 2.4015361e-1f);
    p = fmaf(p, f, 6.9315308e-1f);
    p = fmaf(p, f, 1.0f);
    return __int_as_float(__float_as_int(p) + (n << 23));  // p * 2^n
}

// ---------------- scratch (static device globals; no runtime alloc) ----------
__device__ __align__(16) float g_h[Nn * Dd];
__device__ __align__(16) float g_agg[Nn * Dd];
__device__ __align__(16) float g_hnew[Nn * Dd];
__device__ __align__(16) float g_qkv[Nn * 3 * Dd];
__device__ __align__(16) float g_o[Nn * Dd];
__device__ int   g_deg[Nn];
__device__ float g_degf[Nn];
__device__ int   g_rowptr[Nn + 1];
__device__ int   g_fillpos[Nn];
__device__ int   g_colidx[Ee];

// ---------------- CSR build --------------------------------------------------
__global__ void k_zero_deg() {
    int i = blockIdx.x * blockDim.x + threadIdx.x;
    if (i < Nn) g_deg[i] = 0;
}

__global__ void k_hist(const int* __restrict__ ei) {
    int e = blockIdx.x * blockDim.x + threadIdx.x;
    if (e < Ee) atomicAdd(&g_deg[ei[e]], 1);
}

__global__ void k_scan() {
    __shared__ int s[1024];
    int tid = threadIdx.x;
    int b = tid * 4;
    int v0 = g_deg[b], v1 = g_deg[b + 1], v2 = g_deg[b + 2], v3 = g_deg[b + 3];
    int p1 = v0 + v1, p2 = p1 + v2, p3 = p2 + v3;
    s[tid] = p3;
    __syncthreads();
    for (int off = 1; off < 1024; off <<= 1) {
        int t = (tid >= off) ? s[tid - off] : 0;
        __syncthreads();
        if (tid >= off) s[tid] += t;
        __syncthreads();
    }
    int prev = tid ? s[tid - 1] : 0;
    int e0 = prev, e1 = prev + v0, e2 = prev + p1, e3 = prev + p2;
    g_rowptr[b]     = e0; g_rowptr[b + 1] = e1;
    g_rowptr[b + 2] = e2; g_rowptr[b + 3] = e3;
    g_fillpos[b]     = e0; g_fillpos[b + 1] = e1;
    g_fillpos[b + 2] = e2; g_fillpos[b + 3] = e3;
    g_degf[b]     = (float)v0; g_degf[b + 1] = (float)v1;
    g_degf[b + 2] = (float)v2; g_degf[b + 3] = (float)v3;
    if (tid == 1023) g_rowptr[Nn] = s[1023];
}

__global__ void k_fill(const int* __restrict__ ei) {
    int e = blockIdx.x * blockDim.x + threadIdx.x;
    if (e < Ee) {
        int dst = ei[e];
        int src = ei[Ee + e];
        int pos = atomicAdd(&g_fillpos[dst], 1);
        g_colidx[pos] = src;
    }
}

__global__ void k_copy(const float* __restrict__ emb) {
    int i = blockIdx.x * blockDim.x + threadIdx.x;
    if (i < Nn * Dd / 4)
        ((float4*)g_h)[i] = ((const float4*)emb)[i];
}

// ---------------- neighbor aggregation (warp per node, deterministic) --------
__global__ __launch_bounds__(256) void k_gather() {
    int warp = (blockIdx.x * blockDim.x + threadIdx.x) >> 5;
    int lane = threadIdx.x & 31;
    if (warp >= Nn) return;
    int pbeg = g_rowptr[warp], pend = g_rowptr[warp + 1];
    float4 a0 = {0, 0, 0, 0}, a1 = a0, a2 = a0;
    for (int p = pbeg; p < pend; p++) {
        int src = g_colidx[p];
        const float4* r = (const float4*)(g_h + src * Dd);
        float4 x;
        x = r[lane];      a0.x += x.x; a0.y += x.y; a0.z += x.z; a0.w += x.w;
        x = r[lane + 32]; a1.x += x.x; a1.y += x.y; a1.z += x.z; a1.w += x.w;
        x = r[lane + 64]; a2.x += x.x; a2.y += x.y; a2.z += x.z; a2.w += x.w;
    }
    float4* w = (float4*)(g_agg + warp * Dd);
    w[lane] = a0; w[lane + 32] = a1; w[lane + 64] = a2;
}

// ---------------- GEMM: C[m][n] = sum_k A[m][k]*B[n][k] + epilogue -----------
// 128x64 C-tile, 256 threads, 8x4 micro-tile.
// MODE 0: A=g_agg  -> C=g_hnew, bias scaled by per-row degree        (conv)
// MODE 1: A=g_hnew -> C=g_qkv,  plain bias, Nout=3D                  (qkv)
// MODE 2: A=g_o    -> C=g_h,    bias + residual g_h, relu, in-place  (attn out)
template <int MODE>
__global__ __launch_bounds__(256, 2) void k_gemm(const float* __restrict__ B,
                                                 const float* __restrict__ bias) {
    const float* A;
    float* C;
    int Nout;
    if (MODE == 0)      { A = g_agg;  C = g_hnew; Nout = Dd; }
    else if (MODE == 1) { A = g_hnew; C = g_qkv;  Nout = 3 * Dd; }
    else                { A = g_o;    C = g_h;    Nout = Dd; }

    __shared__ __align__(16) float As[32 * 132];   // [k][m], m-stride 132
    __shared__ __align__(16) float Bs[32 * 68];    // [k][n], n-stride 68
    int tid = threadIdx.x;
    int tx = tid & 15, ty = tid >> 4;
    int row0 = blockIdx.y * 128, col0 = blockIdx.x * 64;

    float acc[8][4];
#pragma unroll
    for (int i = 0; i < 8; i++)
#pragma unroll
        for (int j = 0; j < 4; j++) acc[i][j] = 0.f;

    for (int k0 = 0; k0 < Dd; k0 += 32) {
        // A tile 128x32: per thread 4 x (LDG.128 + 4 scalar transposed STS)
#pragma unroll
        for (int i = tid; i < 1024; i += 256) {
            int m = i & 127, k4 = (i >> 7) * 4;
            float4 a = *(const float4*)&A[(row0 + m) * Dd + k0 + k4];
            As[(k4 + 0) * 132 + m] = a.x;
            As[(k4 + 1) * 132 + m] = a.y;
            As[(k4 + 2) * 132 + m] = a.z;
            As[(k4 + 3) * 132 + m] = a.w;
        }
        // B tile 64x32
#pragma unroll
        for (int i = tid; i < 512; i += 256) {
            int n = i & 63, k4 = (i >> 6) * 4;
            float4 b = *(const float4*)&B[(col0 + n) * Dd + k0 + k4];
            Bs[(k4 + 0) * 68 + n] = b.x;
            Bs[(k4 + 1) * 68 + n] = b.y;
            Bs[(k4 + 2) * 68 + n] = b.z;
            Bs[(k4 + 3) * 68 + n] = b.w;
        }
        __syncthreads();
#pragma unroll 8
        for (int kk = 0; kk < 32; kk++) {
            float4 a0 = *(const float4*)&As[kk * 132 + ty * 8];
            float4 a1 = *(const float4*)&As[kk * 132 + ty * 8 + 4];
            float4 b  = *(const float4*)&Bs[kk * 68 + tx * 4];
            float av[8] = {a0.x, a0.y, a0.z, a0.w, a1.x, a1.y, a1.z, a1.w};
            float bv[4] = {b.x, b.y, b.z, b.w};
#pragma unroll
            for (int i = 0; i < 8; i++)
#pragma unroll
                for (int j = 0; j < 4; j++) acc[i][j] += av[i] * bv[j];
        }
        __syncthreads();
    }

#pragma unroll
    for (int i = 0; i < 8; i++) {
        int m = row0 + ty * 8 + i;
        float rmul = (MODE == 0) ? g_degf[m] : 1.0f;
#pragma unroll
        for (int j = 0; j < 4; j++) {
            int n = col0 + tx * 4 + j;
            float v = acc[i][j] + bias[n] * rmul;
            if (MODE == 2) {
                v += g_h[m * Dd + n];
                v = fmaxf(v, 0.f);
            }
            C[m * Nout + n] = v;
        }
    }
}

// ---------------- flash attention: per (head, 128-query tile), 256 thr -------
// Softmax runs in base-2: log2(e) folded into the Q scale, exp via fexp2
// (polynomial on the FMA pipe — no MUFU).
// smem (floats): Qs[48][128]=6144, Ks[48][64]=3072, Vs[64][48]=3072,
//                Ps[128][68]=8704  -> total 20992 floats = 83968 B (2 blk/SM)
#define QS_OFF 0
#define KS_OFF 6144
#define VS_OFF 9216
#define PS_OFF 12288
#define FLASH_SMEM_FLOATS 20992

__global__ __launch_bounds__(256, 2) void k_flash() {
    extern __shared__ __align__(16) float sm[];
    float* Qs = sm + QS_OFF;
    float* Ks = sm + KS_OFF;
    float* Vs = sm + VS_OFF;
    float* Ps = sm + PS_OFF;
    int head = blockIdx.y;
    int q0 = blockIdx.x * 128;
    int tid = threadIdx.x, tx = tid & 15, ty = tid >> 4;
    // 1/sqrt(48) * log2(e): softmax in base-2
    const float scale = 0.14433756729740643f * 1.4426950408889634f;

    // load Q tile (128 rows x 48 dims) transposed to [d][m], scale folded in
#pragma unroll
    for (int i = tid; i < 128 * 12; i += 256) {
        int m = i / 12, d4 = (i % 12) * 4;
        float4 q = *(const float4*)&g_qkv[(q0 + m) * 1152 + head * 48 + d4];
        Qs[(d4 + 0) * 128 + m] = q.x * scale;
        Qs[(d4 + 1) * 128 + m] = q.y * scale;
        Qs[(d4 + 2) * 128 + m] = q.z * scale;
        Qs[(d4 + 3) * 128 + m] = q.w * scale;
    }

    float mr[8], lr[8], O[8][3];
#pragma unroll
    for (int i = 0; i < 8; i++) {
        mr[i] = -1e30f; lr[i] = 0.f;
        O[i][0] = O[i][1] = O[i][2] = 0.f;
    }

    for (int k0 = 0; k0 < Nn; k0 += 64) {
        __syncthreads();   // guard Vs/Ps reuse from previous iteration
#pragma unroll
        for (int i = tid; i < 64 * 12; i += 256) {
            int n = i / 12, d4 = (i % 12) * 4;
            float4 k = *(const float4*)&g_qkv[(k0 + n) * 1152 + 384 + head * 48 + d4];
            Ks[(d4 + 0) * 64 + n] = k.x;
            Ks[(d4 + 1) * 64 + n] = k.y;
            Ks[(d4 + 2) * 64 + n] = k.z;
            Ks[(d4 + 3) * 64 + n] = k.w;
        }
#pragma unroll
        for (int i = tid; i < 64 * 12; i += 256) {
            int n = i / 12, d4 = (i % 12) * 4;
            *(float4*)&Vs[n * 48 + d4] =
                *(const float4*)&g_qkv[(k0 + n) * 1152 + 768 + head * 48 + d4];
        }
        __syncthreads();

        // S = Q K^T : 8x4 micro-tile (scores already in log2 domain)
        float acc[8][4];
#pragma unroll
        for (int i = 0; i < 8; i++)
#pragma unroll
            for (int j = 0; j < 4; j++) acc[i][j] = 0.f;
#pragma unroll 8
        for (int kk = 0; kk < 48; kk++) {
            float4 a0 = *(const float4*)&Qs[kk * 128 + ty * 8];
            float4 a1 = *(const float4*)&Qs[kk * 128 + ty * 8 + 4];
            float4 b  = *(const float4*)&Ks[kk * 64 + tx * 4];
            float av[8] = {a0.x, a0.y, a0.z, a0.w, a1.x, a1.y, a1.z, a1.w};
            float bv[4] = {b.x, b.y, b.z, b.w};
#pragma unroll
            for (int i = 0; i < 8; i++)
#pragma unroll
                for (int j = 0; j < 4; j++) acc[i][j] += av[i] * bv[j];
        }

        // online softmax (base-2) per row + P store
#pragma unroll
        for (int i = 0; i < 8; i++) {
            float vmax = fmaxf(fmaxf(acc[i][0], acc[i][1]),
                               fmaxf(acc[i][2], acc[i][3]));
#pragma unroll
            for (int off = 8; off; off >>= 1)
                vmax = fmaxf(vmax, __shfl_xor_sync(0xffffffffu, vmax, off));
            float nm = fmaxf(mr[i], vmax);
            float sum = 0.f;
#pragma unroll
            for (int j = 0; j < 4; j++) {
                acc[i][j] = fexp2(acc[i][j] - nm);
                sum += acc[i][j];
            }
#pragma unroll
            for (int off = 8; off; off >>= 1)
                sum += __shfl_xor_sync(0xffffffffu, sum, off);
            float alpha = fexp2(mr[i] - nm);
            lr[i] = lr[i] * alpha + sum;
            mr[i] = nm;
            O[i][0] *= alpha; O[i][1] *= alpha; O[i][2] *= alpha;
            *(float4*)&Ps[(ty * 8 + i) * 68 + tx * 4] =
                make_float4(acc[i][0], acc[i][1], acc[i][2], acc[i][3]);
        }
        __syncwarp();   // P rows for this ty live in this warp only

        // O += P V : chunked over 4 keys, float4 P-row loads, scalar V bcast
        int c0 = tx * 3;
#pragma unroll 2
        for (int j0 = 0; j0 < 64; j0 += 4) {
            float4 p[8];
#pragma unroll
            for (int i = 0; i < 8; i++)
                p[i] = *(const float4*)&Ps[(ty * 8 + i) * 68 + j0];
#pragma unroll
            for (int jj = 0; jj < 4; jj++) {
                const float* vr = &Vs[(j0 + jj) * 48 + c0];
                float v0 = vr[0], v1 = vr[1], v2 = vr[2];
#pragma unroll
                for (int i = 0; i < 8; i++) {
                    float pij = (jj == 0) ? p[i].x : (jj == 1) ? p[i].y
                              : (jj == 2) ? p[i].z : p[i].w;
                    O[i][0] += pij * v0;
                    O[i][1] += pij * v1;
                    O[i][2] += pij * v2;
                }
            }
        }
    }

    // epilogue: normalize + scatter
#pragma unroll
    for (int i = 0; i < 8; i++) {
        float inv = 1.f / lr[i];
        int row = q0 + ty * 8 + i;
        g_o[row * 384 + head * 48 + tx * 3 + 0] = O[i][0] * inv;
        g_o[row * 384 + head * 48 + tx * 3 + 1] = O[i][1] * inv;
        g_o[row * 384 + head * 48 + tx * 3 + 2] = O[i][2] * inv;
    }
}

// ---------------- output projection + sigmoid --------------------------------
__global__ __launch_bounds__(256) void k_out(const float* __restrict__ Wout,
                                             const float* __restrict__ bout,
                                             float* __restrict__ out) {
    int warp = (blockIdx.x * blockDim.x + threadIdx.x) >> 5;
    int lane = threadIdx.x & 31;
    if (warp >= Nn) return;
    const float4* hr = (const float4*)(g_h + warp * Dd);
    const float4* wr = (const float4*)Wout;
    float s = 0.f;
#pragma unroll
    for (int q = 0; q < 3; q++) {
        float4 a = hr[lane + 32 * q];
        float4 b = wr[lane + 32 * q];
        s += a.x * b.x + a.y * b.y + a.z * b.z + a.w * b.w;
    }
#pragma unroll
    for (int off = 16; off; off >>= 1)
        s += __shfl_xor_sync(0xffffffffu, s, off);
    if (lane == 0) out[warp] = 1.f / (1.f + __expf(-(s + bout[0])));
}

// ---------------- launch ------------------------------------------------------
extern "C" void kernel_launch(void* const* d_in, const int* in_sizes, int n_in,
                              void* d_out, int out_size) {
    const float* emb  = (const float*)d_in[0];
    const int*   ei   = (const int*)d_in[1];
    const float* Wc   = (const float*)d_in[2];
    const float* bc   = (const float*)d_in[3];
    const float* Win  = (const float*)d_in[4];
    const float* bin  = (const float*)d_in[5];
    const float* Wao  = (const float*)d_in[6];
    const float* bao  = (const float*)d_in[7];
    const float* Wout = (const float*)d_in[8];
    const float* bout = (const float*)d_in[9];
    float* out = (float*)d_out;

    cudaFuncSetAttribute(k_flash, cudaFuncAttributeMaxDynamicSharedMemorySize,
                         FLASH_SMEM_FLOATS * 4);

    // CSR build (reused across all 3 layers)
    k_zero_deg<<<Nn / 256, 256>>>();
    k_hist<<<Ee / 256, 256>>>(ei);
    k_scan<<<1, 1024>>>();
    k_fill<<<Ee / 256, 256>>>(ei);
    k_copy<<<(Nn * Dd / 4) / 256, 256>>>(emb);

    for (int l = 0; l < Ll; l++) {
        k_gather<<<Nn / 8, 256>>>();
        k_gemm<0><<<dim3(Dd / 64, Nn / 128), 256>>>(Wc + l * Dd * Dd, bc + l * Dd);
        k_gemm<1><<<dim3(3 * Dd / 64, Nn / 128), 256>>>(Win, bin);
        k_flash<<<dim3(Nn / 128, Hh), 256, FLASH_SMEM_FLOATS * 4>>>();
        k_gemm<2><<<dim3(Dd / 64, Nn / 128), 256>>>(Wao, bao);
    }
    k_out<<<Nn / 8, 256>>>(Wout, bout, out);
}

// round 10
// speedup vs baseline: 3.6086x; 1.7046x over previous
#include <cuda_runtime.h>
#include <cuda_bf16.h>
#include <math.h>
#include <stdint.h>

#define Nn 4096
#define Dd 384
#define Ee 131072
#define Hh 8
#define DHh 48
#define Ll 3

// ---------------- fast exp2 on the FMA pipe ----------------------------------
__device__ __forceinline__ float fexp2(float t) {
    t = fmaxf(t, -126.0f);
    float r = t + 12582912.0f;
    int n = __float_as_int(r) - 0x4B400000;
    float f = t - (r - 12582912.0f);
    float p = 1.8775767e-3f;
    p = fmaf(p, f, 8.9893397e-3f);
    p = fmaf(p, f, 5.5826318e-2f);
    p = fmaf(p, f, 2.4015361e-1f);
    p = fmaf(p, f, 6.9315308e-1f);
    p = fmaf(p, f, 1.0f);
    return __int_as_float(__float_as_int(p) + (n << 23));
}

// pack two fp32 -> bf16x2 word (low half = f0)
__device__ __forceinline__ uint32_t bf2(float f0, float f1) {
    uint32_t w;
    asm("cvt.rn.bf16x2.f32 %0, %1, %2;" : "=r"(w) : "f"(f1), "f"(f0));
    return w;
}
__device__ __forceinline__ float lof(uint32_t w) { return __uint_as_float(w << 16); }
__device__ __forceinline__ float hif(uint32_t w) { return __uint_as_float(w & 0xFFFF0000u); }

__device__ __forceinline__ uint32_t s2u(const void* p) {
    return (uint32_t)__cvta_generic_to_shared(p);
}
__device__ __forceinline__ void ldmx4(uint32_t r[4], uint32_t a) {
    asm volatile("ldmatrix.sync.aligned.m8n8.x4.shared.b16 {%0,%1,%2,%3}, [%4];"
                 : "=r"(r[0]), "=r"(r[1]), "=r"(r[2]), "=r"(r[3]) : "r"(a));
}
__device__ __forceinline__ void ldmx4t(uint32_t r[4], uint32_t a) {
    asm volatile("ldmatrix.sync.aligned.m8n8.x4.trans.shared.b16 {%0,%1,%2,%3}, [%4];"
                 : "=r"(r[0]), "=r"(r[1]), "=r"(r[2]), "=r"(r[3]) : "r"(a));
}
__device__ __forceinline__ void mma_bf16(float d[4], const uint32_t a[4],
                                         uint32_t b0, uint32_t b1) {
    asm volatile("mma.sync.aligned.m16n8k16.row.col.f32.bf16.bf16.f32 "
                 "{%0,%1,%2,%3}, {%4,%5,%6,%7}, {%8,%9}, {%0,%1,%2,%3};"
                 : "+f"(d[0]), "+f"(d[1]), "+f"(d[2]), "+f"(d[3])
                 : "r"(a[0]), "r"(a[1]), "r"(a[2]), "r"(a[3]), "r"(b0), "r"(b1));
}

// ---------------- scratch ----------------------------------------------------
__device__ __align__(16) float g_h[Nn * Dd];
__device__ __align__(16) float g_agg[Nn * Dd];
__device__ __align__(16) float g_hnew[Nn * Dd];
__device__ __align__(16) float g_qkv[Nn * 3 * Dd];
__device__ __align__(16) float g_o[Nn * Dd];
__device__ int   g_deg[Nn];
__device__ float g_degf[Nn];
__device__ int   g_rowptr[Nn + 1];
__device__ int   g_fillpos[Nn];
__device__ int   g_colidx[Ee];
// bf16 split tensors: [arr][head][node][48]
__device__ __align__(16) unsigned short g_qs[3 * Hh * Nn * 48];   // Q hi/mid/lo
__device__ __align__(16) unsigned short g_kvs[5 * Hh * Nn * 48];  // K hi/mid/lo, V hi/lo

// ---------------- CSR build --------------------------------------------------
__global__ void k_zero_deg() {
    int i = blockIdx.x * blockDim.x + threadIdx.x;
    if (i < Nn) g_deg[i] = 0;
}
__global__ void k_hist(const int* __restrict__ ei) {
    int e = blockIdx.x * blockDim.x + threadIdx.x;
    if (e < Ee) atomicAdd(&g_deg[ei[e]], 1);
}
__global__ void k_scan() {
    __shared__ int s[1024];
    int tid = threadIdx.x;
    int b = tid * 4;
    int v0 = g_deg[b], v1 = g_deg[b + 1], v2 = g_deg[b + 2], v3 = g_deg[b + 3];
    int p1 = v0 + v1, p2 = p1 + v2, p3 = p2 + v3;
    s[tid] = p3;
    __syncthreads();
    for (int off = 1; off < 1024; off <<= 1) {
        int t = (tid >= off) ? s[tid - off] : 0;
        __syncthreads();
        if (tid >= off) s[tid] += t;
        __syncthreads();
    }
    int prev = tid ? s[tid - 1] : 0;
    int e0 = prev, e1 = prev + v0, e2 = prev + p1, e3 = prev + p2;
    g_rowptr[b] = e0; g_rowptr[b + 1] = e1; g_rowptr[b + 2] = e2; g_rowptr[b + 3] = e3;
    g_fillpos[b] = e0; g_fillpos[b + 1] = e1; g_fillpos[b + 2] = e2; g_fillpos[b + 3] = e3;
    g_degf[b] = (float)v0; g_degf[b + 1] = (float)v1;
    g_degf[b + 2] = (float)v2; g_degf[b + 3] = (float)v3;
    if (tid == 1023) g_rowptr[Nn] = s[1023];
}
__global__ void k_fill(const int* __restrict__ ei) {
    int e = blockIdx.x * blockDim.x + threadIdx.x;
    if (e < Ee) {
        int dst = ei[e];
        int src = ei[Ee + e];
        int pos = atomicAdd(&g_fillpos[dst], 1);
        g_colidx[pos] = src;
    }
}
__global__ void k_copy(const float* __restrict__ emb) {
    int i = blockIdx.x * blockDim.x + threadIdx.x;
    if (i < Nn * Dd / 4)
        ((float4*)g_h)[i] = ((const float4*)emb)[i];
}

// ---------------- neighbor aggregation ---------------------------------------
__global__ __launch_bounds__(256) void k_gather() {
    int warp = (blockIdx.x * blockDim.x + threadIdx.x) >> 5;
    int lane = threadIdx.x & 31;
    if (warp >= Nn) return;
    int pbeg = g_rowptr[warp], pend = g_rowptr[warp + 1];
    float4 a0 = {0, 0, 0, 0}, a1 = a0, a2 = a0;
    for (int p = pbeg; p < pend; p++) {
        int src = g_colidx[p];
        const float4* r = (const float4*)(g_h + src * Dd);
        float4 x;
        x = r[lane];      a0.x += x.x; a0.y += x.y; a0.z += x.z; a0.w += x.w;
        x = r[lane + 32]; a1.x += x.x; a1.y += x.y; a1.z += x.z; a1.w += x.w;
        x = r[lane + 64]; a2.x += x.x; a2.y += x.y; a2.z += x.z; a2.w += x.w;
    }
    float4* w = (float4*)(g_agg + warp * Dd);
    w[lane] = a0; w[lane + 32] = a1; w[lane + 64] = a2;
}

// ---------------- GEMM (scalar fp32, R8) -------------------------------------
template <int MODE>
__global__ __launch_bounds__(256, 2) void k_gemm(const float* __restrict__ B,
                                                 const float* __restrict__ bias) {
    const float* A;
    float* C;
    int Nout;
    if (MODE == 0)      { A = g_agg;  C = g_hnew; Nout = Dd; }
    else if (MODE == 1) { A = g_hnew; C = g_qkv;  Nout = 3 * Dd; }
    else                { A = g_o;    C = g_h;    Nout = Dd; }

    __shared__ __align__(16) float As[32 * 132];
    __shared__ __align__(16) float Bs[32 * 68];
    int tid = threadIdx.x;
    int tx = tid & 15, ty = tid >> 4;
    int row0 = blockIdx.y * 128, col0 = blockIdx.x * 64;

    float acc[8][4];
#pragma unroll
    for (int i = 0; i < 8; i++)
#pragma unroll
        for (int j = 0; j < 4; j++) acc[i][j] = 0.f;

    for (int k0 = 0; k0 < Dd; k0 += 32) {
#pragma unroll
        for (int i = tid; i < 1024; i += 256) {
            int m = i & 127, k4 = (i >> 7) * 4;
            float4 a = *(const float4*)&A[(row0 + m) * Dd + k0 + k4];
            As[(k4 + 0) * 132 + m] = a.x;
            As[(k4 + 1) * 132 + m] = a.y;
            As[(k4 + 2) * 132 + m] = a.z;
            As[(k4 + 3) * 132 + m] = a.w;
        }
#pragma unroll
        for (int i = tid; i < 512; i += 256) {
            int n = i & 63, k4 = (i >> 6) * 4;
            float4 b = *(const float4*)&B[(col0 + n) * Dd + k0 + k4];
            Bs[(k4 + 0) * 68 + n] = b.x;
            Bs[(k4 + 1) * 68 + n] = b.y;
            Bs[(k4 + 2) * 68 + n] = b.z;
            Bs[(k4 + 3) * 68 + n] = b.w;
        }
        __syncthreads();
#pragma unroll 8
        for (int kk = 0; kk < 32; kk++) {
            float4 a0 = *(const float4*)&As[kk * 132 + ty * 8];
            float4 a1 = *(const float4*)&As[kk * 132 + ty * 8 + 4];
            float4 b  = *(const float4*)&Bs[kk * 68 + tx * 4];
            float av[8] = {a0.x, a0.y, a0.z, a0.w, a1.x, a1.y, a1.z, a1.w};
            float bv[4] = {b.x, b.y, b.z, b.w};
#pragma unroll
            for (int i = 0; i < 8; i++)
#pragma unroll
                for (int j = 0; j < 4; j++) acc[i][j] += av[i] * bv[j];
        }
        __syncthreads();
    }

#pragma unroll
    for (int i = 0; i < 8; i++) {
        int m = row0 + ty * 8 + i;
        float rmul = (MODE == 0) ? g_degf[m] : 1.0f;
#pragma unroll
        for (int j = 0; j < 4; j++) {
            int n = col0 + tx * 4 + j;
            float v = acc[i][j] + bias[n] * rmul;
            if (MODE == 2) {
                v += g_h[m * Dd + n];
                v = fmaxf(v, 0.f);
            }
            C[m * Nout + n] = v;
        }
    }
}

// ---------------- split qkv into bf16 hi/mid/lo --------------------------------
__global__ __launch_bounds__(256) void k_split() {
    int i = blockIdx.x * 256 + threadIdx.x;    // < Nn*96
    int node = i / 96;
    int c4 = i - node * 96;
    int dglob = c4 * 4;
    int head = dglob / 48;
    int d = dglob - head * 48;
    int dsti = ((head * Nn) + node) * 48 + d;
    const int SEC = Hh * Nn * 48;
    const float qscale = 0.14433756729740643f * 1.4426950408889634f;

    float4 q = *(const float4*)&g_qkv[node * 1152 + dglob];
    float4 k = *(const float4*)&g_qkv[node * 1152 + 384 + dglob];
    float4 v = *(const float4*)&g_qkv[node * 1152 + 768 + dglob];
    q.x *= qscale; q.y *= qscale; q.z *= qscale; q.w *= qscale;

    // Q split-3
    {
        uint32_t wa0 = bf2(q.x, q.y), wa1 = bf2(q.z, q.w);
        *(uint2*)&g_qs[dsti] = make_uint2(wa0, wa1);
        float r0 = q.x - lof(wa0), r1 = q.y - hif(wa0);
        float r2 = q.z - lof(wa1), r3 = q.w - hif(wa1);
        uint32_t wb0 = bf2(r0, r1), wb1 = bf2(r2, r3);
        *(uint2*)&g_qs[SEC + dsti] = make_uint2(wb0, wb1);
        uint32_t wc0 = bf2(r0 - lof(wb0), r1 - hif(wb0));
        uint32_t wc1 = bf2(r2 - lof(wb1), r3 - hif(wb1));
        *(uint2*)&g_qs[2 * SEC + dsti] = make_uint2(wc0, wc1);
    }
    // K split-3
    {
        uint32_t wa0 = bf2(k.x, k.y), wa1 = bf2(k.z, k.w);
        *(uint2*)&g_kvs[dsti] = make_uint2(wa0, wa1);
        float r0 = k.x - lof(wa0), r1 = k.y - hif(wa0);
        float r2 = k.z - lof(wa1), r3 = k.w - hif(wa1);
        uint32_t wb0 = bf2(r0, r1), wb1 = bf2(r2, r3);
        *(uint2*)&g_kvs[SEC + dsti] = make_uint2(wb0, wb1);
        uint32_t wc0 = bf2(r0 - lof(wb0), r1 - hif(wb0));
        uint32_t wc1 = bf2(r2 - lof(wb1), r3 - hif(wb1));
        *(uint2*)&g_kvs[2 * SEC + dsti] = make_uint2(wc0, wc1);
    }
    // V split-2
    {
        uint32_t wa0 = bf2(v.x, v.y), wa1 = bf2(v.z, v.w);
        *(uint2*)&g_kvs[3 * SEC + dsti] = make_uint2(wa0, wa1);
        uint32_t wb0 = bf2(v.x - lof(wa0), v.y - hif(wa0));
        uint32_t wb1 = bf2(v.z - lof(wa1), v.w - hif(wa1));
        *(uint2*)&g_kvs[4 * SEC + dsti] = make_uint2(wb0, wb1);
    }
}

// ---------------- mma.sync flash attention -----------------------------------
// CTA = (head, 128 queries), 8 warps x 16 rows, 64-key tiles.
// smem: sQ[3] 128x64 bf16 (16KB each) @0; sK[3] 64x64 (8KB) @49152;
//       sV[2] 64x64 (8KB) @73728. Total 90112 B. XOR swizzle on 16B chunks.
#define FL_SMEM 90112

__global__ __launch_bounds__(256, 2) void k_flash_mma() {
    extern __shared__ __align__(128) char sm[];
    uint32_t smb = s2u(sm);
    const int tid = threadIdx.x, lane = tid & 31, w = tid >> 5;
    const int head = blockIdx.y, q0 = blockIdx.x * 128;
    const int hN = head * Nn;
    const int SEC = Hh * Nn * 48;

    // stage Q (3 splits x 128 rows x 6 chunks)
    for (int i = tid; i < 2304; i += 256) {
        int arr = i / 768, rem = i - arr * 768;
        int row = rem / 6, c = rem - row * 6;
        uint4 val = *(const uint4*)(g_qs + arr * SEC + (hN + q0 + row) * 48 + c * 8);
        *(uint4*)(sm + arr * 16384 + row * 128 + ((c * 16) ^ ((row & 7) * 16))) = val;
    }

    float of[6][4];
#pragma unroll
    for (int n = 0; n < 6; n++)
#pragma unroll
        for (int j = 0; j < 4; j++) of[n][j] = 0.f;
    float mr0 = -1e30f, mr1 = -1e30f, lr0 = 0.f, lr1 = 0.f;

    // ldmatrix lane-address components
    const int l15 = lane & 15, l7 = lane & 7;
    const int lhi = lane >> 4;           // 0/1: second matrix pair
    const int lmid = (lane >> 3) & 1;    // for K chunk selection

    for (int kt = 0; kt < 64; kt++) {
        int k0 = kt * 64;
        __syncthreads();
        // stage K (3x64x6) + V (2x64x6) = 1920 chunks
        for (int i = tid; i < 1920; i += 256) {
            int arr = i / 384, rem = i - arr * 384;
            int row = rem / 6, c = rem - row * 6;
            uint4 val = *(const uint4*)(g_kvs + arr * SEC + (hN + k0 + row) * 48 + c * 8);
            *(uint4*)(sm + 49152 + arr * 8192 + row * 128 +
                      ((c * 16) ^ ((row & 7) * 16))) = val;
        }
        __syncthreads();

        // ---- S = sum of 6 bf16 split terms ----
        float sf[8][4];
#pragma unroll
        for (int nt = 0; nt < 8; nt++)
#pragma unroll
            for (int j = 0; j < 4; j++) sf[nt][j] = 0.f;

#pragma unroll
        for (int ks = 0; ks < 3; ks++) {
#pragma unroll
            for (int kk = 0; kk < 3; kk++) {
                uint32_t Bf[8][2];
#pragma unroll
                for (int np = 0; np < 4; np++) {
                    int key = 8 * (2 * np + lhi) + l7;
                    int ch = 2 * ks + lmid;
                    uint32_t r[4];
                    ldmx4(r, smb + 49152 + kk * 8192 + key * 128 +
                             ((ch * 16) ^ ((key & 7) * 16)));
                    Bf[2 * np][0] = r[0]; Bf[2 * np][1] = r[1];
                    Bf[2 * np + 1][0] = r[2]; Bf[2 * np + 1][1] = r[3];
                }
                int nq = (kk == 0) ? 3 : ((kk == 1) ? 2 : 1);
                for (int qs = 0; qs < nq; qs++) {
                    int row = 16 * w + l15;
                    int ch = 2 * ks + lhi;
                    uint32_t A[4];
                    ldmx4(A, smb + qs * 16384 + row * 128 +
                             ((ch * 16) ^ ((row & 7) * 16)));
#pragma unroll
                    for (int nt = 0; nt < 8; nt++)
                        mma_bf16(sf[nt], A, Bf[nt][0], Bf[nt][1]);
                }
            }
        }

        // ---- online softmax (base-2), rows r0 = 16w+(lane>>2), r1 = r0+8 ----
        float vmax0 = -1e30f, vmax1 = -1e30f;
#pragma unroll
        for (int nt = 0; nt < 8; nt++) {
            vmax0 = fmaxf(vmax0, fmaxf(sf[nt][0], sf[nt][1]));
            vmax1 = fmaxf(vmax1, fmaxf(sf[nt][2], sf[nt][3]));
        }
        vmax0 = fmaxf(vmax0, __shfl_xor_sync(0xffffffffu, vmax0, 1));
        vmax0 = fmaxf(vmax0, __shfl_xor_sync(0xffffffffu, vmax0, 2));
        vmax1 = fmaxf(vmax1, __shfl_xor_sync(0xffffffffu, vmax1, 1));
        vmax1 = fmaxf(vmax1, __shfl_xor_sync(0xffffffffu, vmax1, 2));
        float nm0 = fmaxf(mr0, vmax0), nm1 = fmaxf(mr1, vmax1);
        float al0 = fexp2(mr0 - nm0), al1 = fexp2(mr1 - nm1);
        mr0 = nm0; mr1 = nm1;

        uint32_t pA[4][4];
        float ps0 = 0.f, ps1 = 0.f;
#pragma unroll
        for (int t = 0; t < 4; t++) {
            float p00 = fexp2(sf[2 * t][0] - nm0), p01 = fexp2(sf[2 * t][1] - nm0);
            float p10 = fexp2(sf[2 * t][2] - nm1), p11 = fexp2(sf[2 * t][3] - nm1);
            float p20 = fexp2(sf[2 * t + 1][0] - nm0), p21 = fexp2(sf[2 * t + 1][1] - nm0);
            float p30 = fexp2(sf[2 * t + 1][2] - nm1), p31 = fexp2(sf[2 * t + 1][3] - nm1);
            uint32_t w0 = bf2(p00, p01), w1 = bf2(p10, p11);
            uint32_t w2 = bf2(p20, p21), w3 = bf2(p30, p31);
            pA[t][0] = w0; pA[t][1] = w1; pA[t][2] = w2; pA[t][3] = w3;
            ps0 += lof(w0) + hif(w0) + lof(w2) + hif(w2);
            ps1 += lof(w1) + hif(w1) + lof(w3) + hif(w3);
        }
        ps0 += __shfl_xor_sync(0xffffffffu, ps0, 1);
        ps0 += __shfl_xor_sync(0xffffffffu, ps0, 2);
        ps1 += __shfl_xor_sync(0xffffffffu, ps1, 1);
        ps1 += __shfl_xor_sync(0xffffffffu, ps1, 2);
        lr0 = lr0 * al0 + ps0;
        lr1 = lr1 * al1 + ps1;
#pragma unroll
        for (int n = 0; n < 6; n++) {
            of[n][0] *= al0; of[n][1] *= al0;
            of[n][2] *= al1; of[n][3] *= al1;
        }

        // ---- O += P V  (V via ldmatrix.trans, 2 splits) ----
#pragma unroll
        for (int t = 0; t < 4; t++) {
#pragma unroll
            for (int vs = 0; vs < 2; vs++) {
#pragma unroll
                for (int np = 0; np < 3; np++) {
                    int key = 16 * t + l15;
                    int ch = 2 * np + lhi;
                    uint32_t r[4];
                    ldmx4t(r, smb + 73728 + vs * 8192 + key * 128 +
                              ((ch * 16) ^ ((key & 7) * 16)));
                    mma_bf16(of[2 * np], pA[t], r[0], r[1]);
                    mma_bf16(of[2 * np + 1], pA[t], r[2], r[3]);
                }
            }
        }
    }

    // ---- epilogue: normalize + store ----
    float inv0 = 1.f / lr0, inv1 = 1.f / lr1;
    int r0 = q0 + 16 * w + (lane >> 2), r1 = r0 + 8;
    int cb = head * 48 + (lane & 3) * 2;
#pragma unroll
    for (int n = 0; n < 6; n++) {
        *(float2*)&g_o[r0 * 384 + cb + n * 8] =
            make_float2(of[n][0] * inv0, of[n][1] * inv0);
        *(float2*)&g_o[r1 * 384 + cb + n * 8] =
            make_float2(of[n][2] * inv1, of[n][3] * inv1);
    }
}

// ---------------- output projection + sigmoid --------------------------------
__global__ __launch_bounds__(256) void k_out(const float* __restrict__ Wout,
                                             const float* __restrict__ bout,
                                             float* __restrict__ out) {
    int warp = (blockIdx.x * blockDim.x + threadIdx.x) >> 5;
    int lane = threadIdx.x & 31;
    if (warp >= Nn) return;
    const float4* hr = (const float4*)(g_h + warp * Dd);
    const float4* wr = (const float4*)Wout;
    float s = 0.f;
#pragma unroll
    for (int q = 0; q < 3; q++) {
        float4 a = hr[lane + 32 * q];
        float4 b = wr[lane + 32 * q];
        s += a.x * b.x + a.y * b.y + a.z * b.z + a.w * b.w;
    }
#pragma unroll
    for (int off = 16; off; off >>= 1)
        s += __shfl_xor_sync(0xffffffffu, s, off);
    if (lane == 0) out[warp] = 1.f / (1.f + __expf(-(s + bout[0])));
}

// ---------------- launch ------------------------------------------------------
extern "C" void kernel_launch(void* const* d_in, const int* in_sizes, int n_in,
                              void* d_out, int out_size) {
    const float* emb  = (const float*)d_in[0];
    const int*   ei   = (const int*)d_in[1];
    const float* Wc   = (const float*)d_in[2];
    const float* bc   = (const float*)d_in[3];
    const float* Win  = (const float*)d_in[4];
    const float* bin  = (const float*)d_in[5];
    const float* Wao  = (const float*)d_in[6];
    const float* bao  = (const float*)d_in[7];
    const float* Wout = (const float*)d_in[8];
    const float* bout = (const float*)d_in[9];
    float* out = (float*)d_out;

    cudaFuncSetAttribute(k_flash_mma, cudaFuncAttributeMaxDynamicSharedMemorySize,
                         FL_SMEM);

    // CSR build (reused across all 3 layers)
    k_zero_deg<<<Nn / 256, 256>>>();
    k_hist<<<Ee / 256, 256>>>(ei);
    k_scan<<<1, 1024>>>();
    k_fill<<<Ee / 256, 256>>>(ei);
    k_copy<<<(Nn * Dd / 4) / 256, 256>>>(emb);

    for (int l = 0; l < Ll; l++) {
        k_gather<<<Nn / 8, 256>>>();
        k_gemm<0><<<dim3(Dd / 64, Nn / 128), 256>>>(Wc + l * Dd * Dd, bc + l * Dd);
        k_gemm<1><<<dim3(3 * Dd / 64, Nn / 128), 256>>>(Win, bin);
        k_split<<<(Nn * 96) / 256, 256>>>();
        k_flash_mma<<<dim3(Nn / 128, Hh), 256, FL_SMEM>>>();
        k_gemm<2><<<dim3(Dd / 64, Nn / 128), 256>>>(Wao, bao);
    }
    k_out<<<Nn / 8, 256>>>(Wout, bout, out);
}

// round 11
// speedup vs baseline: 3.6224x; 1.0038x over previous
#include <cuda_runtime.h>
#include <cuda_bf16.h>
#include <math.h>
#include <stdint.h>

#define Nn 4096
#define Dd 384
#define Ee 131072
#define Hh 8
#define DHh 48
#define Ll 3

// ---------------- fast exp2 on the FMA pipe ----------------------------------
__device__ __forceinline__ float fexp2(float t) {
    t = fmaxf(t, -126.0f);
    float r = t + 12582912.0f;
    int n = __float_as_int(r) - 0x4B400000;
    float f = t - (r - 12582912.0f);
    float p = 1.8775767e-3f;
    p = fmaf(p, f, 8.9893397e-3f);
    p = fmaf(p, f, 5.5826318e-2f);
    p = fmaf(p, f, 2.4015361e-1f);
    p = fmaf(p, f, 6.9315308e-1f);
    p = fmaf(p, f, 1.0f);
    return __int_as_float(__float_as_int(p) + (n << 23));
}

// pack two fp32 -> bf16x2 word (low half = f0)
__device__ __forceinline__ uint32_t bf2(float f0, float f1) {
    uint32_t w;
    asm("cvt.rn.bf16x2.f32 %0, %1, %2;" : "=r"(w) : "f"(f1), "f"(f0));
    return w;
}
__device__ __forceinline__ float lof(uint32_t w) { return __uint_as_float(w << 16); }
__device__ __forceinline__ float hif(uint32_t w) { return __uint_as_float(w & 0xFFFF0000u); }

__device__ __forceinline__ uint32_t s2u(const void* p) {
    return (uint32_t)__cvta_generic_to_shared(p);
}
__device__ __forceinline__ void ldmx4(uint32_t r[4], uint32_t a) {
    asm volatile("ldmatrix.sync.aligned.m8n8.x4.shared.b16 {%0,%1,%2,%3}, [%4];"
                 : "=r"(r[0]), "=r"(r[1]), "=r"(r[2]), "=r"(r[3]) : "r"(a));
}
__device__ __forceinline__ void ldmx4t(uint32_t r[4], uint32_t a) {
    asm volatile("ldmatrix.sync.aligned.m8n8.x4.trans.shared.b16 {%0,%1,%2,%3}, [%4];"
                 : "=r"(r[0]), "=r"(r[1]), "=r"(r[2]), "=r"(r[3]) : "r"(a));
}
__device__ __forceinline__ void mma_bf16(float d[4], const uint32_t a[4],
                                         uint32_t b0, uint32_t b1) {
    asm volatile("mma.sync.aligned.m16n8k16.row.col.f32.bf16.bf16.f32 "
                 "{%0,%1,%2,%3}, {%4,%5,%6,%7}, {%8,%9}, {%0,%1,%2,%3};"
                 : "+f"(d[0]), "+f"(d[1]), "+f"(d[2]), "+f"(d[3])
                 : "r"(a[0]), "r"(a[1]), "r"(a[2]), "r"(a[3]), "r"(b0), "r"(b1));
}

// ---------------- scratch ----------------------------------------------------
__device__ __align__(16) float g_h[Nn * Dd];
__device__ __align__(16) float g_qkv[Nn * 3 * Dd];
__device__ int   g_deg[Nn];
__device__ float g_degf[Nn];
__device__ int   g_rowptr[Nn + 1];
__device__ int   g_fillpos[Nn];
__device__ int   g_colidx[Ee];
// bf16 split-3 activation buffers, layout [plane][node*384+col]
__device__ __align__(16) unsigned short g_sA[3][Nn * Dd];  // gather out (agg)
__device__ __align__(16) unsigned short g_sB[3][Nn * Dd];  // conv out  (hnew)
__device__ __align__(16) unsigned short g_sC[3][Nn * Dd];  // flash out (o)
// bf16 split-3 weights: conv(l) @ l*147456, Win @ 442368, Wao @ 884736
#define WTOT 1032192
#define OFF_CONV(l) ((l) * Dd * Dd)
#define OFF_WIN (3 * Dd * Dd)
#define OFF_WAO (3 * Dd * Dd + 3 * Dd * Dd)
__device__ __align__(16) unsigned short g_ws[3][WTOT];
// flash-side Q/K/V split tensors: [arr][head][node][48]
__device__ __align__(16) unsigned short g_qs[3 * Hh * Nn * 48];   // Q hi/mid/lo
__device__ __align__(16) unsigned short g_kvs[5 * Hh * Nn * 48];  // K hi/mid/lo, V hi/lo

// split (v0,v1) into 3 bf16x2 words stored to the 3 planes at element idx
template <typename PT>
__device__ __forceinline__ void split3_pair(PT planes, int idx, float v0, float v1) {
    uint32_t w0 = bf2(v0, v1);
    *(uint32_t*)&planes[0][idx] = w0;
    float r0 = v0 - lof(w0), r1 = v1 - hif(w0);
    uint32_t w1 = bf2(r0, r1);
    *(uint32_t*)&planes[1][idx] = w1;
    *(uint32_t*)&planes[2][idx] = bf2(r0 - lof(w1), r1 - hif(w1));
}

// ---------------- CSR build --------------------------------------------------
__global__ void k_zero_deg() {
    int i = blockIdx.x * blockDim.x + threadIdx.x;
    if (i < Nn) g_deg[i] = 0;
}
__global__ void k_hist(const int* __restrict__ ei) {
    int e = blockIdx.x * blockDim.x + threadIdx.x;
    if (e < Ee) atomicAdd(&g_deg[ei[e]], 1);
}
__global__ void k_scan() {
    __shared__ int s[1024];
    int tid = threadIdx.x;
    int b = tid * 4;
    int v0 = g_deg[b], v1 = g_deg[b + 1], v2 = g_deg[b + 2], v3 = g_deg[b + 3];
    int p1 = v0 + v1, p2 = p1 + v2, p3 = p2 + v3;
    s[tid] = p3;
    __syncthreads();
    for (int off = 1; off < 1024; off <<= 1) {
        int t = (tid >= off) ? s[tid - off] : 0;
        __syncthreads();
        if (tid >= off) s[tid] += t;
        __syncthreads();
    }
    int prev = tid ? s[tid - 1] : 0;
    int e0 = prev, e1 = prev + v0, e2 = prev + p1, e3 = prev + p2;
    g_rowptr[b] = e0; g_rowptr[b + 1] = e1; g_rowptr[b + 2] = e2; g_rowptr[b + 3] = e3;
    g_fillpos[b] = e0; g_fillpos[b + 1] = e1; g_fillpos[b + 2] = e2; g_fillpos[b + 3] = e3;
    g_degf[b] = (float)v0; g_degf[b + 1] = (float)v1;
    g_degf[b + 2] = (float)v2; g_degf[b + 3] = (float)v3;
    if (tid == 1023) g_rowptr[Nn] = s[1023];
}
__global__ void k_fill(const int* __restrict__ ei) {
    int e = blockIdx.x * blockDim.x + threadIdx.x;
    if (e < Ee) {
        int dst = ei[e];
        int src = ei[Ee + e];
        int pos = atomicAdd(&g_fillpos[dst], 1);
        g_colidx[pos] = src;
    }
}
__global__ void k_copy(const float* __restrict__ emb) {
    int i = blockIdx.x * blockDim.x + threadIdx.x;
    if (i < Nn * Dd / 4)
        ((float4*)g_h)[i] = ((const float4*)emb)[i];
}

// ---------------- weight split (once per launch) ------------------------------
__global__ __launch_bounds__(256) void k_wsplit(const float* __restrict__ src,
                                                int dstoff, int n4) {
    int i = blockIdx.x * 256 + threadIdx.x;
    if (i >= n4) return;
    float4 x = ((const float4*)src)[i];
    int idx = dstoff + i * 4;
    split3_pair(g_ws, idx, x.x, x.y);
    split3_pair(g_ws, idx + 2, x.z, x.w);
}

// ---------------- neighbor aggregation -> split-3 bf16 ------------------------
__global__ __launch_bounds__(256) void k_gather() {
    int warp = (blockIdx.x * blockDim.x + threadIdx.x) >> 5;
    int lane = threadIdx.x & 31;
    if (warp >= Nn) return;
    int pbeg = g_rowptr[warp], pend = g_rowptr[warp + 1];
    float4 a0 = {0, 0, 0, 0}, a1 = a0, a2 = a0;
    for (int p = pbeg; p < pend; p++) {
        int src = g_colidx[p];
        const float4* r = (const float4*)(g_h + src * Dd);
        float4 x;
        x = r[lane];      a0.x += x.x; a0.y += x.y; a0.z += x.z; a0.w += x.w;
        x = r[lane + 32]; a1.x += x.x; a1.y += x.y; a1.z += x.z; a1.w += x.w;
        x = r[lane + 64]; a2.x += x.x; a2.y += x.y; a2.z += x.z; a2.w += x.w;
    }
    int base = warp * Dd + lane * 4;
    split3_pair(g_sA, base, a0.x, a0.y);
    split3_pair(g_sA, base + 2, a0.z, a0.w);
    split3_pair(g_sA, base + 128, a1.x, a1.y);
    split3_pair(g_sA, base + 130, a1.z, a1.w);
    split3_pair(g_sA, base + 256, a2.x, a2.y);
    split3_pair(g_sA, base + 258, a2.z, a2.w);
}

// ---------------- mma.sync GEMM: C = A * B^T + epilogue ------------------------
// A: split-3 bf16 [Nn][384]; B: split-3 bf16 weights [N][384] at g_ws+woff.
// C tile 128x64, 8 warps. Terms {00,01,02,10,11,20} -> rel err ~2^-26.
// MODE 0: A=g_sA -> split-3 g_sB, bias*degf          (conv)
// MODE 1: A=g_sB -> fp32 g_qkv, bias, Nout=1152      (qkv)
// MODE 2: A=g_sC -> fp32 g_h, bias+residual+relu     (attn out)
#define GM_SMEM 73728

template <int MODE>
__global__ __launch_bounds__(256, 2) void k_gemm_mma(int woff,
                                                     const float* __restrict__ bias) {
    extern __shared__ __align__(128) char sm[];
    uint32_t smb = s2u(sm);
    const int tid = threadIdx.x, lane = tid & 31, w = tid >> 5;
    const int row0 = blockIdx.y * 128, col0 = blockIdx.x * 64;
    const int l15 = lane & 15, l7 = lane & 7;
    const int lhi = lane >> 4, lmid = (lane >> 3) & 1;

    float of[8][4];
#pragma unroll
    for (int i = 0; i < 8; i++)
#pragma unroll
        for (int j = 0; j < 4; j++) of[i][j] = 0.f;

    for (int kc = 0; kc < 6; kc++) {
        __syncthreads();
        // stage A: 3 planes x 128 rows x 8 chunks
        for (int i = tid; i < 3072; i += 256) {
            int arr = i >> 10, rem = i & 1023;
            int row = rem >> 3, ch = rem & 7;
            const unsigned short* ap = (MODE == 0) ? g_sA[arr]
                                     : (MODE == 1) ? g_sB[arr] : g_sC[arr];
            uint4 val = *(const uint4*)(ap + (row0 + row) * 384 + kc * 64 + ch * 8);
            *(uint4*)(sm + arr * 16384 + row * 128 + ((ch * 16) ^ ((row & 7) * 16))) = val;
        }
        // stage B: 3 planes x 64 rows x 8 chunks
        for (int i = tid; i < 1536; i += 256) {
            int arr = i >> 9, rem = i & 511;
            int n = rem >> 3, ch = rem & 7;
            uint4 val = *(const uint4*)(g_ws[arr] + woff + (col0 + n) * 384 +
                                        kc * 64 + ch * 8);
            *(uint4*)(sm + 49152 + arr * 8192 + n * 128 +
                      ((ch * 16) ^ ((n & 7) * 16))) = val;
        }
        __syncthreads();

#pragma unroll
        for (int asp = 0; asp < 3; asp++) {
            uint32_t Af[4][4];
#pragma unroll
            for (int kst = 0; kst < 4; kst++) {
                int row = 16 * w + l15, ch = 2 * kst + lhi;
                ldmx4(Af[kst], smb + asp * 16384 + row * 128 +
                               ((ch * 16) ^ ((row & 7) * 16)));
            }
            int nb = (asp == 0) ? 3 : ((asp == 1) ? 2 : 1);
            for (int bsp = 0; bsp < nb; bsp++) {
#pragma unroll
                for (int kst = 0; kst < 4; kst++) {
#pragma unroll
                    for (int np = 0; np < 4; np++) {
                        int key = 8 * (2 * np + lhi) + l7, ch = 2 * kst + lmid;
                        uint32_t r[4];
                        ldmx4(r, smb + 49152 + bsp * 8192 + key * 128 +
                                 ((ch * 16) ^ ((key & 7) * 16)));
                        mma_bf16(of[2 * np], Af[kst], r[0], r[1]);
                        mma_bf16(of[2 * np + 1], Af[kst], r[2], r[3]);
                    }
                }
            }
        }
    }

    // epilogue
    int r0 = row0 + 16 * w + (lane >> 2), r1 = r0 + 8;
    int cbl = (lane & 3) * 2;
    float dg0 = (MODE == 0) ? g_degf[r0] : 1.f;
    float dg1 = (MODE == 0) ? g_degf[r1] : 1.f;
#pragma unroll
    for (int nt = 0; nt < 8; nt++) {
        int n = col0 + nt * 8 + cbl;
        float b0 = bias[n], b1 = bias[n + 1];
        float v00 = of[nt][0] + b0 * dg0, v01 = of[nt][1] + b1 * dg0;
        float v10 = of[nt][2] + b0 * dg1, v11 = of[nt][3] + b1 * dg1;
        if (MODE == 0) {
            split3_pair(g_sB, r0 * 384 + n, v00, v01);
            split3_pair(g_sB, r1 * 384 + n, v10, v11);
        } else if (MODE == 1) {
            *(float2*)&g_qkv[r0 * 1152 + n] = make_float2(v00, v01);
            *(float2*)&g_qkv[r1 * 1152 + n] = make_float2(v10, v11);
        } else {
            float2 h0 = *(const float2*)&g_h[r0 * 384 + n];
            float2 h1 = *(const float2*)&g_h[r1 * 384 + n];
            *(float2*)&g_h[r0 * 384 + n] =
                make_float2(fmaxf(v00 + h0.x, 0.f), fmaxf(v01 + h0.y, 0.f));
            *(float2*)&g_h[r1 * 384 + n] =
                make_float2(fmaxf(v10 + h1.x, 0.f), fmaxf(v11 + h1.y, 0.f));
        }
    }
}

// ---------------- split qkv into flash-side bf16 arrays -----------------------
__global__ __launch_bounds__(256) void k_split() {
    int i = blockIdx.x * 256 + threadIdx.x;    // < Nn*96
    int node = i / 96;
    int c4 = i - node * 96;
    int dglob = c4 * 4;
    int head = dglob / 48;
    int d = dglob - head * 48;
    int dsti = ((head * Nn) + node) * 48 + d;
    const int SEC = Hh * Nn * 48;
    const float qscale = 0.14433756729740643f * 1.4426950408889634f;

    float4 q = *(const float4*)&g_qkv[node * 1152 + dglob];
    float4 k = *(const float4*)&g_qkv[node * 1152 + 384 + dglob];
    float4 v = *(const float4*)&g_qkv[node * 1152 + 768 + dglob];
    q.x *= qscale; q.y *= qscale; q.z *= qscale; q.w *= qscale;

    // Q split-3
    {
        uint32_t wa0 = bf2(q.x, q.y), wa1 = bf2(q.z, q.w);
        *(uint2*)&g_qs[dsti] = make_uint2(wa0, wa1);
        float r0 = q.x - lof(wa0), r1 = q.y - hif(wa0);
        float r2 = q.z - lof(wa1), r3 = q.w - hif(wa1);
        uint32_t wb0 = bf2(r0, r1), wb1 = bf2(r2, r3);
        *(uint2*)&g_qs[SEC + dsti] = make_uint2(wb0, wb1);
        uint32_t wc0 = bf2(r0 - lof(wb0), r1 - hif(wb0));
        uint32_t wc1 = bf2(r2 - lof(wb1), r3 - hif(wb1));
        *(uint2*)&g_qs[2 * SEC + dsti] = make_uint2(wc0, wc1);
    }
    // K split-3
    {
        uint32_t wa0 = bf2(k.x, k.y), wa1 = bf2(k.z, k.w);
        *(uint2*)&g_kvs[dsti] = make_uint2(wa0, wa1);
        float r0 = k.x - lof(wa0), r1 = k.y - hif(wa0);
        float r2 = k.z - lof(wa1), r3 = k.w - hif(wa1);
        uint32_t wb0 = bf2(r0, r1), wb1 = bf2(r2, r3);
        *(uint2*)&g_kvs[SEC + dsti] = make_uint2(wb0, wb1);
        uint32_t wc0 = bf2(r0 - lof(wb0), r1 - hif(wb0));
        uint32_t wc1 = bf2(r2 - lof(wb1), r3 - hif(wb1));
        *(uint2*)&g_kvs[2 * SEC + dsti] = make_uint2(wc0, wc1);
    }
    // V split-2
    {
        uint32_t wa0 = bf2(v.x, v.y), wa1 = bf2(v.z, v.w);
        *(uint2*)&g_kvs[3 * SEC + dsti] = make_uint2(wa0, wa1);
        uint32_t wb0 = bf2(v.x - lof(wa0), v.y - hif(wa0));
        uint32_t wb1 = bf2(v.z - lof(wa1), v.w - hif(wa1));
        *(uint2*)&g_kvs[4 * SEC + dsti] = make_uint2(wb0, wb1);
    }
}

// ---------------- mma.sync flash attention -----------------------------------
#define FL_SMEM 90112

__global__ __launch_bounds__(256, 2) void k_flash_mma() {
    extern __shared__ __align__(128) char sm[];
    uint32_t smb = s2u(sm);
    const int tid = threadIdx.x, lane = tid & 31, w = tid >> 5;
    const int head = blockIdx.y, q0 = blockIdx.x * 128;
    const int hN = head * Nn;
    const int SEC = Hh * Nn * 48;

    // stage Q (3 splits x 128 rows x 6 chunks)
    for (int i = tid; i < 2304; i += 256) {
        int arr = i / 768, rem = i - arr * 768;
        int row = rem / 6, c = rem - row * 6;
        uint4 val = *(const uint4*)(g_qs + arr * SEC + (hN + q0 + row) * 48 + c * 8);
        *(uint4*)(sm + arr * 16384 + row * 128 + ((c * 16) ^ ((row & 7) * 16))) = val;
    }

    float of[6][4];
#pragma unroll
    for (int n = 0; n < 6; n++)
#pragma unroll
        for (int j = 0; j < 4; j++) of[n][j] = 0.f;
    float mr0 = -1e30f, mr1 = -1e30f, lr0 = 0.f, lr1 = 0.f;

    const int l15 = lane & 15, l7 = lane & 7;
    const int lhi = lane >> 4;
    const int lmid = (lane >> 3) & 1;

    for (int kt = 0; kt < 64; kt++) {
        int k0 = kt * 64;
        __syncthreads();
        for (int i = tid; i < 1920; i += 256) {
            int arr = i / 384, rem = i - arr * 384;
            int row = rem / 6, c = rem - row * 6;
            uint4 val = *(const uint4*)(g_kvs + arr * SEC + (hN + k0 + row) * 48 + c * 8);
            *(uint4*)(sm + 49152 + arr * 8192 + row * 128 +
                      ((c * 16) ^ ((row & 7) * 16))) = val;
        }
        __syncthreads();

        // ---- S = sum of 6 bf16 split terms ----
        float sf[8][4];
#pragma unroll
        for (int nt = 0; nt < 8; nt++)
#pragma unroll
            for (int j = 0; j < 4; j++) sf[nt][j] = 0.f;

#pragma unroll
        for (int ks = 0; ks < 3; ks++) {
#pragma unroll
            for (int kk = 0; kk < 3; kk++) {
                uint32_t Bf[8][2];
#pragma unroll
                for (int np = 0; np < 4; np++) {
                    int key = 8 * (2 * np + lhi) + l7;
                    int ch = 2 * ks + lmid;
                    uint32_t r[4];
                    ldmx4(r, smb + 49152 + kk * 8192 + key * 128 +
                             ((ch * 16) ^ ((key & 7) * 16)));
                    Bf[2 * np][0] = r[0]; Bf[2 * np][1] = r[1];
                    Bf[2 * np + 1][0] = r[2]; Bf[2 * np + 1][1] = r[3];
                }
                int nq = (kk == 0) ? 3 : ((kk == 1) ? 2 : 1);
                for (int qs = 0; qs < nq; qs++) {
                    int row = 16 * w + l15;
                    int ch = 2 * ks + lhi;
                    uint32_t A[4];
                    ldmx4(A, smb + qs * 16384 + row * 128 +
                             ((ch * 16) ^ ((row & 7) * 16)));
#pragma unroll
                    for (int nt = 0; nt < 8; nt++)
                        mma_bf16(sf[nt], A, Bf[nt][0], Bf[nt][1]);
                }
            }
        }

        // ---- online softmax (base-2) ----
        float vmax0 = -1e30f, vmax1 = -1e30f;
#pragma unroll
        for (int nt = 0; nt < 8; nt++) {
            vmax0 = fmaxf(vmax0, fmaxf(sf[nt][0], sf[nt][1]));
            vmax1 = fmaxf(vmax1, fmaxf(sf[nt][2], sf[nt][3]));
        }
        vmax0 = fmaxf(vmax0, __shfl_xor_sync(0xffffffffu, vmax0, 1));
        vmax0 = fmaxf(vmax0, __shfl_xor_sync(0xffffffffu, vmax0, 2));
        vmax1 = fmaxf(vmax1, __shfl_xor_sync(0xffffffffu, vmax1, 1));
        vmax1 = fmaxf(vmax1, __shfl_xor_sync(0xffffffffu, vmax1, 2));
        float nm0 = fmaxf(mr0, vmax0), nm1 = fmaxf(mr1, vmax1);
        float al0 = fexp2(mr0 - nm0), al1 = fexp2(mr1 - nm1);
        mr0 = nm0; mr1 = nm1;

        uint32_t pA[4][4];
        float ps0 = 0.f, ps1 = 0.f;
#pragma unroll
        for (int t = 0; t < 4; t++) {
            float p00 = fexp2(sf[2 * t][0] - nm0), p01 = fexp2(sf[2 * t][1] - nm0);
            float p10 = fexp2(sf[2 * t][2] - nm1), p11 = fexp2(sf[2 * t][3] - nm1);
            float p20 = fexp2(sf[2 * t + 1][0] - nm0), p21 = fexp2(sf[2 * t + 1][1] - nm0);
            float p30 = fexp2(sf[2 * t + 1][2] - nm1), p31 = fexp2(sf[2 * t + 1][3] - nm1);
            uint32_t w0 = bf2(p00, p01), w1 = bf2(p10, p11);
            uint32_t w2 = bf2(p20, p21), w3 = bf2(p30, p31);
            pA[t][0] = w0; pA[t][1] = w1; pA[t][2] = w2; pA[t][3] = w3;
            ps0 += lof(w0) + hif(w0) + lof(w2) + hif(w2);
            ps1 += lof(w1) + hif(w1) + lof(w3) + hif(w3);
        }
        ps0 += __shfl_xor_sync(0xffffffffu, ps0, 1);
        ps0 += __shfl_xor_sync(0xffffffffu, ps0, 2);
        ps1 += __shfl_xor_sync(0xffffffffu, ps1, 1);
        ps1 += __shfl_xor_sync(0xffffffffu, ps1, 2);
        lr0 = lr0 * al0 + ps0;
        lr1 = lr1 * al1 + ps1;
#pragma unroll
        for (int n = 0; n < 6; n++) {
            of[n][0] *= al0; of[n][1] *= al0;
            of[n][2] *= al1; of[n][3] *= al1;
        }

        // ---- O += P V ----
#pragma unroll
        for (int t = 0; t < 4; t++) {
#pragma unroll
            for (int vs = 0; vs < 2; vs++) {
#pragma unroll
                for (int np = 0; np < 3; np++) {
                    int key = 16 * t + l15;
                    int ch = 2 * np + lhi;
                    uint32_t r[4];
                    ldmx4t(r, smb + 73728 + vs * 8192 + key * 128 +
                              ((ch * 16) ^ ((key & 7) * 16)));
                    mma_bf16(of[2 * np], pA[t], r[0], r[1]);
                    mma_bf16(of[2 * np + 1], pA[t], r[2], r[3]);
                }
            }
        }
    }

    // ---- epilogue: normalize + split-3 store to g_sC ----
    float inv0 = 1.f / lr0, inv1 = 1.f / lr1;
    int r0 = q0 + 16 * w + (lane >> 2), r1 = r0 + 8;
    int cb = head * 48 + (lane & 3) * 2;
#pragma unroll
    for (int n = 0; n < 6; n++) {
        split3_pair(g_sC, r0 * 384 + cb + n * 8, of[n][0] * inv0, of[n][1] * inv0);
        split3_pair(g_sC, r1 * 384 + cb + n * 8, of[n][2] * inv1, of[n][3] * inv1);
    }
}

// ---------------- output projection + sigmoid --------------------------------
__global__ __launch_bounds__(256) void k_out(const float* __restrict__ Wout,
                                             const float* __restrict__ bout,
                                             float* __restrict__ out) {
    int warp = (blockIdx.x * blockDim.x + threadIdx.x) >> 5;
    int lane = threadIdx.x & 31;
    if (warp >= Nn) return;
    const float4* hr = (const float4*)(g_h + warp * Dd);
    const float4* wr = (const float4*)Wout;
    float s = 0.f;
#pragma unroll
    for (int q = 0; q < 3; q++) {
        float4 a = hr[lane + 32 * q];
        float4 b = wr[lane + 32 * q];
        s += a.x * b.x + a.y * b.y + a.z * b.z + a.w * b.w;
    }
#pragma unroll
    for (int off = 16; off; off >>= 1)
        s += __shfl_xor_sync(0xffffffffu, s, off);
    if (lane == 0) out[warp] = 1.f / (1.f + __expf(-(s + bout[0])));
}

// ---------------- launch ------------------------------------------------------
extern "C" void kernel_launch(void* const* d_in, const int* in_sizes, int n_in,
                              void* d_out, int out_size) {
    const float* emb  = (const float*)d_in[0];
    const int*   ei   = (const int*)d_in[1];
    const float* Wc   = (const float*)d_in[2];
    const float* bc   = (const float*)d_in[3];
    const float* Win  = (const float*)d_in[4];
    const float* bin  = (const float*)d_in[5];
    const float* Wao  = (const float*)d_in[6];
    const float* bao  = (const float*)d_in[7];
    const float* Wout = (const float*)d_in[8];
    const float* bout = (const float*)d_in[9];
    float* out = (float*)d_out;

    cudaFuncSetAttribute(k_flash_mma, cudaFuncAttributeMaxDynamicSharedMemorySize,
                         FL_SMEM);
    cudaFuncSetAttribute(k_gemm_mma<0>, cudaFuncAttributeMaxDynamicSharedMemorySize,
                         GM_SMEM);
    cudaFuncSetAttribute(k_gemm_mma<1>, cudaFuncAttributeMaxDynamicSharedMemorySize,
                         GM_SMEM);
    cudaFuncSetAttribute(k_gemm_mma<2>, cudaFuncAttributeMaxDynamicSharedMemorySize,
                         GM_SMEM);

    // CSR build + weight splits (reused across all 3 layers)
    k_zero_deg<<<Nn / 256, 256>>>();
    k_hist<<<Ee / 256, 256>>>(ei);
    k_scan<<<1, 1024>>>();
    k_fill<<<Ee / 256, 256>>>(ei);
    k_copy<<<(Nn * Dd / 4) / 256, 256>>>(emb);
    k_wsplit<<<432, 256>>>(Wc, 0, 3 * Dd * Dd / 4);            // conv x3 layers
    k_wsplit<<<432, 256>>>(Win, OFF_WIN, 3 * Dd * Dd / 4);     // Win (1152x384)
    k_wsplit<<<144, 256>>>(Wao, OFF_WAO, Dd * Dd / 4);         // Wao

    for (int l = 0; l < Ll; l++) {
        k_gather<<<Nn / 8, 256>>>();
        k_gemm_mma<0><<<dim3(Dd / 64, Nn / 128), 256, GM_SMEM>>>(OFF_CONV(l),
                                                                 bc + l * Dd);
        k_gemm_mma<1><<<dim3(3 * Dd / 64, Nn / 128), 256, GM_SMEM>>>(OFF_WIN, bin);
        k_split<<<(Nn * 96) / 256, 256>>>();
        k_flash_mma<<<dim3(Nn / 128, Hh), 256, FL_SMEM>>>();
        k_gemm_mma<2><<<dim3(Dd / 64, Nn / 128), 256, GM_SMEM>>>(OFF_WAO, bao);
    }
    k_out<<<Nn / 8, 256>>>(Wout, bout, out);
}

// round 12
// speedup vs baseline: 3.7003x; 1.0215x over previous
#include <cuda_runtime.h>
#include <cuda_bf16.h>
#include <math.h>
#include <stdint.h>

#define Nn 4096
#define Dd 384
#define Ee 131072
#define Hh 8
#define DHh 48
#define Ll 3
#define SEC (Hh * Nn * 48)

// ---------------- fast exp2 on the FMA pipe ----------------------------------
__device__ __forceinline__ float fexp2(float t) {
    t = fmaxf(t, -126.0f);
    float r = t + 12582912.0f;
    int n = __float_as_int(r) - 0x4B400000;
    float f = t - (r - 12582912.0f);
    float p = 1.8775767e-3f;
    p = fmaf(p, f, 8.9893397e-3f);
    p = fmaf(p, f, 5.5826318e-2f);
    p = fmaf(p, f, 2.4015361e-1f);
    p = fmaf(p, f, 6.9315308e-1f);
    p = fmaf(p, f, 1.0f);
    return __int_as_float(__float_as_int(p) + (n << 23));
}

// pack two fp32 -> bf16x2 word (low half = f0)
__device__ __forceinline__ uint32_t bf2(float f0, float f1) {
    uint32_t w;
    asm("cvt.rn.bf16x2.f32 %0, %1, %2;" : "=r"(w) : "f"(f1), "f"(f0));
    return w;
}
__device__ __forceinline__ float lof(uint32_t w) { return __uint_as_float(w << 16); }
__device__ __forceinline__ float hif(uint32_t w) { return __uint_as_float(w & 0xFFFF0000u); }

__device__ __forceinline__ uint32_t s2u(const void* p) {
    return (uint32_t)__cvta_generic_to_shared(p);
}
__device__ __forceinline__ void ldmx4(uint32_t r[4], uint32_t a) {
    asm volatile("ldmatrix.sync.aligned.m8n8.x4.shared.b16 {%0,%1,%2,%3}, [%4];"
                 : "=r"(r[0]), "=r"(r[1]), "=r"(r[2]), "=r"(r[3]) : "r"(a));
}
__device__ __forceinline__ void ldmx4t(uint32_t r[4], uint32_t a) {
    asm volatile("ldmatrix.sync.aligned.m8n8.x4.trans.shared.b16 {%0,%1,%2,%3}, [%4];"
                 : "=r"(r[0]), "=r"(r[1]), "=r"(r[2]), "=r"(r[3]) : "r"(a));
}
__device__ __forceinline__ void mma_bf16(float d[4], const uint32_t a[4],
                                         uint32_t b0, uint32_t b1) {
    asm volatile("mma.sync.aligned.m16n8k16.row.col.f32.bf16.bf16.f32 "
                 "{%0,%1,%2,%3}, {%4,%5,%6,%7}, {%8,%9}, {%0,%1,%2,%3};"
                 : "+f"(d[0]), "+f"(d[1]), "+f"(d[2]), "+f"(d[3])
                 : "r"(a[0]), "r"(a[1]), "r"(a[2]), "r"(a[3]), "r"(b0), "r"(b1));
}
__device__ __forceinline__ void cpasync16(uint32_t dst, const void* src) {
    asm volatile("cp.async.cg.shared.global [%0], [%1], 16;" :: "r"(dst), "l"(src));
}

// ---------------- scratch ----------------------------------------------------
__device__ __align__(16) float g_h[Nn * Dd];
__device__ int   g_deg[Nn];
__device__ float g_degf[Nn];
__device__ int   g_rowptr[Nn + 1];
__device__ int   g_fillpos[Nn];
__device__ int   g_colidx[Ee];
// bf16 split-3 activation buffers, layout [plane][node*384+col]
__device__ __align__(16) unsigned short g_sA[3][Nn * Dd];  // gather out (agg)
__device__ __align__(16) unsigned short g_sB[3][Nn * Dd];  // conv out  (hnew)
__device__ __align__(16) unsigned short g_sC[3][Nn * Dd];  // flash out (o)
// bf16 split-3 weights
#define WTOT 1032192
#define OFF_CONV(l) ((l) * Dd * Dd)
#define OFF_WIN (3 * Dd * Dd)
#define OFF_WAO (3 * Dd * Dd + 3 * Dd * Dd)
__device__ __align__(16) unsigned short g_ws[3][WTOT];
// flash-side Q/K/V split tensors: [arr][head][node][48]
__device__ __align__(16) unsigned short g_qs[3 * SEC];   // Q hi/mid/lo
__device__ __align__(16) unsigned short g_kvs[5 * SEC];  // K hi/mid/lo, V hi/lo

// split (v0,v1) into 3 bf16x2 planes of a [3][...] array
template <typename PT>
__device__ __forceinline__ void split3_pair(PT planes, int idx, float v0, float v1) {
    uint32_t w0 = bf2(v0, v1);
    *(uint32_t*)&planes[0][idx] = w0;
    float r0 = v0 - lof(w0), r1 = v1 - hif(w0);
    uint32_t w1 = bf2(r0, r1);
    *(uint32_t*)&planes[1][idx] = w1;
    *(uint32_t*)&planes[2][idx] = bf2(r0 - lof(w1), r1 - hif(w1));
}
// strided variants (base + plane*stride)
__device__ __forceinline__ void split3s(unsigned short* base, int stride, int idx,
                                        float v0, float v1) {
    uint32_t w0 = bf2(v0, v1);
    *(uint32_t*)&base[idx] = w0;
    float r0 = v0 - lof(w0), r1 = v1 - hif(w0);
    uint32_t w1 = bf2(r0, r1);
    *(uint32_t*)&base[stride + idx] = w1;
    *(uint32_t*)&base[2 * stride + idx] = bf2(r0 - lof(w1), r1 - hif(w1));
}
__device__ __forceinline__ void split2s(unsigned short* base, int stride, int idx,
                                        float v0, float v1) {
    uint32_t w0 = bf2(v0, v1);
    *(uint32_t*)&base[idx] = w0;
    *(uint32_t*)&base[stride + idx] = bf2(v0 - lof(w0), v1 - hif(w0));
}

// ---------------- CSR build --------------------------------------------------
__global__ void k_zero_deg() {
    int i = blockIdx.x * blockDim.x + threadIdx.x;
    if (i < Nn) g_deg[i] = 0;
}
__global__ void k_hist(const int* __restrict__ ei) {
    int e = blockIdx.x * blockDim.x + threadIdx.x;
    if (e < Ee) atomicAdd(&g_deg[ei[e]], 1);
}
__global__ void k_scan() {
    __shared__ int s[1024];
    int tid = threadIdx.x;
    int b = tid * 4;
    int v0 = g_deg[b], v1 = g_deg[b + 1], v2 = g_deg[b + 2], v3 = g_deg[b + 3];
    int p1 = v0 + v1, p2 = p1 + v2, p3 = p2 + v3;
    s[tid] = p3;
    __syncthreads();
    for (int off = 1; off < 1024; off <<= 1) {
        int t = (tid >= off) ? s[tid - off] : 0;
        __syncthreads();
        if (tid >= off) s[tid] += t;
        __syncthreads();
    }
    int prev = tid ? s[tid - 1] : 0;
    int e0 = prev, e1 = prev + v0, e2 = prev + p1, e3 = prev + p2;
    g_rowptr[b] = e0; g_rowptr[b + 1] = e1; g_rowptr[b + 2] = e2; g_rowptr[b + 3] = e3;
    g_fillpos[b] = e0; g_fillpos[b + 1] = e1; g_fillpos[b + 2] = e2; g_fillpos[b + 3] = e3;
    g_degf[b] = (float)v0; g_degf[b + 1] = (float)v1;
    g_degf[b + 2] = (float)v2; g_degf[b + 3] = (float)v3;
    if (tid == 1023) g_rowptr[Nn] = s[1023];
}
__global__ void k_fill(const int* __restrict__ ei) {
    int e = blockIdx.x * blockDim.x + threadIdx.x;
    if (e < Ee) {
        int dst = ei[e];
        int src = ei[Ee + e];
        int pos = atomicAdd(&g_fillpos[dst], 1);
        g_colidx[pos] = src;
    }
}
__global__ void k_copy(const float* __restrict__ emb) {
    int i = blockIdx.x * blockDim.x + threadIdx.x;
    if (i < Nn * Dd / 4)
        ((float4*)g_h)[i] = ((const float4*)emb)[i];
}

// ---------------- weight split (once per launch) ------------------------------
__global__ __launch_bounds__(256) void k_wsplit(const float* __restrict__ src,
                                                int dstoff, int n4) {
    int i = blockIdx.x * 256 + threadIdx.x;
    if (i >= n4) return;
    float4 x = ((const float4*)src)[i];
    int idx = dstoff + i * 4;
    split3_pair(g_ws, idx, x.x, x.y);
    split3_pair(g_ws, idx + 2, x.z, x.w);
}

// ---------------- neighbor aggregation -> split-3 bf16 ------------------------
__global__ __launch_bounds__(256) void k_gather() {
    int warp = (blockIdx.x * blockDim.x + threadIdx.x) >> 5;
    int lane = threadIdx.x & 31;
    if (warp >= Nn) return;
    int pbeg = g_rowptr[warp], pend = g_rowptr[warp + 1];
    float4 a0 = {0, 0, 0, 0}, a1 = a0, a2 = a0;
    for (int p = pbeg; p < pend; p++) {
        int src = g_colidx[p];
        const float4* r = (const float4*)(g_h + src * Dd);
        float4 x;
        x = r[lane];      a0.x += x.x; a0.y += x.y; a0.z += x.z; a0.w += x.w;
        x = r[lane + 32]; a1.x += x.x; a1.y += x.y; a1.z += x.z; a1.w += x.w;
        x = r[lane + 64]; a2.x += x.x; a2.y += x.y; a2.z += x.z; a2.w += x.w;
    }
    int base = warp * Dd + lane * 4;
    split3_pair(g_sA, base, a0.x, a0.y);
    split3_pair(g_sA, base + 2, a0.z, a0.w);
    split3_pair(g_sA, base + 128, a1.x, a1.y);
    split3_pair(g_sA, base + 130, a1.z, a1.w);
    split3_pair(g_sA, base + 256, a2.x, a2.y);
    split3_pair(g_sA, base + 258, a2.z, a2.w);
}

// ---------------- mma.sync GEMM: C = A * B^T + epilogue ------------------------
// MODE 0: A=g_sA -> split-3 g_sB, bias*degf               (conv)
// MODE 1: A=g_sB -> split q/k/v directly into g_qs/g_kvs  (qkv + fused split)
// MODE 2: A=g_sC -> fp32 g_h, bias+residual+relu          (attn out)
#define GM_SMEM 73728

template <int MODE>
__global__ __launch_bounds__(256, 2) void k_gemm_mma(int woff,
                                                     const float* __restrict__ bias) {
    extern __shared__ __align__(128) char sm[];
    uint32_t smb = s2u(sm);
    const int tid = threadIdx.x, lane = tid & 31, w = tid >> 5;
    const int row0 = blockIdx.y * 128, col0 = blockIdx.x * 64;
    const int l15 = lane & 15, l7 = lane & 7;
    const int lhi = lane >> 4, lmid = (lane >> 3) & 1;

    float of[8][4];
#pragma unroll
    for (int i = 0; i < 8; i++)
#pragma unroll
        for (int j = 0; j < 4; j++) of[i][j] = 0.f;

    for (int kc = 0; kc < 6; kc++) {
        __syncthreads();
        for (int i = tid; i < 3072; i += 256) {
            int arr = i >> 10, rem = i & 1023;
            int row = rem >> 3, ch = rem & 7;
            const unsigned short* ap = (MODE == 0) ? g_sA[arr]
                                     : (MODE == 1) ? g_sB[arr] : g_sC[arr];
            uint4 val = *(const uint4*)(ap + (row0 + row) * 384 + kc * 64 + ch * 8);
            *(uint4*)(sm + arr * 16384 + row * 128 + ((ch * 16) ^ ((row & 7) * 16))) = val;
        }
        for (int i = tid; i < 1536; i += 256) {
            int arr = i >> 9, rem = i & 511;
            int n = rem >> 3, ch = rem & 7;
            uint4 val = *(const uint4*)(g_ws[arr] + woff + (col0 + n) * 384 +
                                        kc * 64 + ch * 8);
            *(uint4*)(sm + 49152 + arr * 8192 + n * 128 +
                      ((ch * 16) ^ ((n & 7) * 16))) = val;
        }
        __syncthreads();

#pragma unroll
        for (int asp = 0; asp < 3; asp++) {
            uint32_t Af[4][4];
#pragma unroll
            for (int kst = 0; kst < 4; kst++) {
                int row = 16 * w + l15, ch = 2 * kst + lhi;
                ldmx4(Af[kst], smb + asp * 16384 + row * 128 +
                               ((ch * 16) ^ ((row & 7) * 16)));
            }
            int nb = (asp == 0) ? 3 : ((asp == 1) ? 2 : 1);
            for (int bsp = 0; bsp < nb; bsp++) {
#pragma unroll
                for (int kst = 0; kst < 4; kst++) {
#pragma unroll
                    for (int np = 0; np < 4; np++) {
                        int key = 8 * (2 * np + lhi) + l7, ch = 2 * kst + lmid;
                        uint32_t r[4];
                        ldmx4(r, smb + 49152 + bsp * 8192 + key * 128 +
                                 ((ch * 16) ^ ((key & 7) * 16)));
                        mma_bf16(of[2 * np], Af[kst], r[0], r[1]);
                        mma_bf16(of[2 * np + 1], Af[kst], r[2], r[3]);
                    }
                }
            }
        }
    }

    // epilogue
    const float qscale = 0.14433756729740643f * 1.4426950408889634f;
    int r0 = row0 + 16 * w + (lane >> 2), r1 = r0 + 8;
    int cbl = (lane & 3) * 2;
    float dg0 = (MODE == 0) ? g_degf[r0] : 1.f;
    float dg1 = (MODE == 0) ? g_degf[r1] : 1.f;
#pragma unroll
    for (int nt = 0; nt < 8; nt++) {
        int n = col0 + nt * 8 + cbl;
        float b0 = bias[n], b1 = bias[n + 1];
        float v00 = of[nt][0] + b0 * dg0, v01 = of[nt][1] + b1 * dg0;
        float v10 = of[nt][2] + b0 * dg1, v11 = of[nt][3] + b1 * dg1;
        if (MODE == 0) {
            split3_pair(g_sB, r0 * 384 + n, v00, v01);
            split3_pair(g_sB, r1 * 384 + n, v10, v11);
        } else if (MODE == 1) {
            int sec = n / 384;
            int wn = n - sec * 384;
            int hd = wn / 48, d = wn - hd * 48;
            int i0 = (hd * Nn + r0) * 48 + d;
            int i1 = (hd * Nn + r1) * 48 + d;
            if (sec == 0) {
                split3s(g_qs, SEC, i0, v00 * qscale, v01 * qscale);
                split3s(g_qs, SEC, i1, v10 * qscale, v11 * qscale);
            } else if (sec == 1) {
                split3s(g_kvs, SEC, i0, v00, v01);
                split3s(g_kvs, SEC, i1, v10, v11);
            } else {
                split2s(g_kvs + 3 * SEC, SEC, i0, v00, v01);
                split2s(g_kvs + 3 * SEC, SEC, i1, v10, v11);
            }
        } else {
            float2 h0 = *(const float2*)&g_h[r0 * 384 + n];
            float2 h1 = *(const float2*)&g_h[r1 * 384 + n];
            *(float2*)&g_h[r0 * 384 + n] =
                make_float2(fmaxf(v00 + h0.x, 0.f), fmaxf(v01 + h0.y, 0.f));
            *(float2*)&g_h[r1 * 384 + n] =
                make_float2(fmaxf(v10 + h1.x, 0.f), fmaxf(v11 + h1.y, 0.f));
        }
    }
}

// ---------------- mma.sync flash attention (pipelined) ------------------------
// Q A-fragments in registers (direct global loads); K/V double-buffered via
// cp.async. smem = 2 x 40960 B (K 3x8KB + V 2x8KB per buffer).
#define FL_SMEM 81920

__device__ __forceinline__ void flash_stage(uint32_t smb, int hN, int k0,
                                            int buf, int tid) {
    for (int i = tid; i < 1920; i += 256) {
        int arr = i / 384, rem = i - arr * 384;
        int row = rem / 6, c = rem - row * 6;
        const unsigned short* src = g_kvs + arr * SEC + (hN + k0 + row) * 48 + c * 8;
        uint32_t dst = smb + buf * 40960 + arr * 8192 + row * 128 +
                       ((c * 16) ^ ((row & 7) * 16));
        cpasync16(dst, src);
    }
    asm volatile("cp.async.commit_group;" ::: "memory");
}

__global__ __launch_bounds__(256, 2) void k_flash_mma() {
    extern __shared__ __align__(128) char sm[];
    uint32_t smb = s2u(sm);
    const int tid = threadIdx.x, lane = tid & 31, w = tid >> 5;
    const int head = blockIdx.y, q0 = blockIdx.x * 128;
    const int hN = head * Nn;
    const int l15 = lane & 15, l7 = lane & 7;
    const int lhi = lane >> 4, lmid = (lane >> 3) & 1;

    // Q A-fragments direct from global (row=16w+g(+8), col=16ks+2t(+8))
    uint32_t qf[3][3][4];
    {
        int rl = 16 * w + (lane >> 2);
        int cq = (lane & 3) * 2;
#pragma unroll
        for (int qs = 0; qs < 3; qs++) {
            const unsigned short* qp = g_qs + qs * SEC + (hN + q0) * 48;
#pragma unroll
            for (int ks = 0; ks < 3; ks++) {
                int c = 16 * ks + cq;
                qf[qs][ks][0] = *(const uint32_t*)&qp[rl * 48 + c];
                qf[qs][ks][1] = *(const uint32_t*)&qp[(rl + 8) * 48 + c];
                qf[qs][ks][2] = *(const uint32_t*)&qp[rl * 48 + c + 8];
                qf[qs][ks][3] = *(const uint32_t*)&qp[(rl + 8) * 48 + c + 8];
            }
        }
    }

    float of[6][4];
#pragma unroll
    for (int n = 0; n < 6; n++)
#pragma unroll
        for (int j = 0; j < 4; j++) of[n][j] = 0.f;
    float mr0 = -1e30f, mr1 = -1e30f, lr0 = 0.f, lr1 = 0.f;

    flash_stage(smb, hN, 0, 0, tid);   // prologue: tile 0 in flight

    for (int kt = 0; kt < 64; kt++) {
        int buf = kt & 1;
        uint32_t kvb = smb + buf * 40960;
        if (kt + 1 < 64)
            flash_stage(smb, hN, (kt + 1) * 64, buf ^ 1, tid);
        else
            asm volatile("cp.async.commit_group;" ::: "memory");
        asm volatile("cp.async.wait_group 1;" ::: "memory");
        __syncthreads();

        // ---- S = sum of 6 bf16 split terms ----
        float sf[8][4];
#pragma unroll
        for (int nt = 0; nt < 8; nt++)
#pragma unroll
            for (int j = 0; j < 4; j++) sf[nt][j] = 0.f;

#pragma unroll
        for (int ks = 0; ks < 3; ks++) {
#pragma unroll
            for (int kk = 0; kk < 3; kk++) {
                uint32_t Bf[8][2];
#pragma unroll
                for (int np = 0; np < 4; np++) {
                    int key = 8 * (2 * np + lhi) + l7;
                    int ch = 2 * ks + lmid;
                    uint32_t r[4];
                    ldmx4(r, kvb + kk * 8192 + key * 128 +
                             ((ch * 16) ^ ((key & 7) * 16)));
                    Bf[2 * np][0] = r[0]; Bf[2 * np][1] = r[1];
                    Bf[2 * np + 1][0] = r[2]; Bf[2 * np + 1][1] = r[3];
                }
#pragma unroll
                for (int qs = 0; qs < 3; qs++) {
                    if (qs + kk <= 2) {
#pragma unroll
                        for (int nt = 0; nt < 8; nt++)
                            mma_bf16(sf[nt], qf[qs][ks], Bf[nt][0], Bf[nt][1]);
                    }
                }
            }
        }

        // ---- online softmax (base-2) ----
        float vmax0 = -1e30f, vmax1 = -1e30f;
#pragma unroll
        for (int nt = 0; nt < 8; nt++) {
            vmax0 = fmaxf(vmax0, fmaxf(sf[nt][0], sf[nt][1]));
            vmax1 = fmaxf(vmax1, fmaxf(sf[nt][2], sf[nt][3]));
        }
        vmax0 = fmaxf(vmax0, __shfl_xor_sync(0xffffffffu, vmax0, 1));
        vmax0 = fmaxf(vmax0, __shfl_xor_sync(0xffffffffu, vmax0, 2));
        vmax1 = fmaxf(vmax1, __shfl_xor_sync(0xffffffffu, vmax1, 1));
        vmax1 = fmaxf(vmax1, __shfl_xor_sync(0xffffffffu, vmax1, 2));
        float nm0 = fmaxf(mr0, vmax0), nm1 = fmaxf(mr1, vmax1);
        float al0 = fexp2(mr0 - nm0), al1 = fexp2(mr1 - nm1);
        mr0 = nm0; mr1 = nm1;

        uint32_t pA[4][4];
        float ps0 = 0.f, ps1 = 0.f;
#pragma unroll
        for (int t = 0; t < 4; t++) {
            float p00 = fexp2(sf[2 * t][0] - nm0), p01 = fexp2(sf[2 * t][1] - nm0);
            float p10 = fexp2(sf[2 * t][2] - nm1), p11 = fexp2(sf[2 * t][3] - nm1);
            float p20 = fexp2(sf[2 * t + 1][0] - nm0), p21 = fexp2(sf[2 * t + 1][1] - nm0);
            float p30 = fexp2(sf[2 * t + 1][2] - nm1), p31 = fexp2(sf[2 * t + 1][3] - nm1);
            uint32_t w0 = bf2(p00, p01), w1 = bf2(p10, p11);
            uint32_t w2 = bf2(p20, p21), w3 = bf2(p30, p31);
            pA[t][0] = w0; pA[t][1] = w1; pA[t][2] = w2; pA[t][3] = w3;
            ps0 += lof(w0) + hif(w0) + lof(w2) + hif(w2);
            ps1 += lof(w1) + hif(w1) + lof(w3) + hif(w3);
        }
        ps0 += __shfl_xor_sync(0xffffffffu, ps0, 1);
        ps0 += __shfl_xor_sync(0xffffffffu, ps0, 2);
        ps1 += __shfl_xor_sync(0xffffffffu, ps1, 1);
        ps1 += __shfl_xor_sync(0xffffffffu, ps1, 2);
        lr0 = lr0 * al0 + ps0;
        lr1 = lr1 * al1 + ps1;
#pragma unroll
        for (int n = 0; n < 6; n++) {
            of[n][0] *= al0; of[n][1] *= al0;
            of[n][2] *= al1; of[n][3] *= al1;
        }

        // ---- O += P V ----
#pragma unroll
        for (int t = 0; t < 4; t++) {
#pragma unroll
            for (int vs = 0; vs < 2; vs++) {
#pragma unroll
                for (int np = 0; np < 3; np++) {
                    int key = 16 * t + l15;
                    int ch = 2 * np + lhi;
                    uint32_t r[4];
                    ldmx4t(r, kvb + 24576 + vs * 8192 + key * 128 +
                              ((ch * 16) ^ ((key & 7) * 16)));
                    mma_bf16(of[2 * np], pA[t], r[0], r[1]);
                    mma_bf16(of[2 * np + 1], pA[t], r[2], r[3]);
                }
            }
        }
        __syncthreads();
    }

    // ---- epilogue: normalize + split-3 store to g_sC ----
    float inv0 = 1.f / lr0, inv1 = 1.f / lr1;
    int r0 = q0 + 16 * w + (lane >> 2), r1 = r0 + 8;
    int cb = head * 48 + (lane & 3) * 2;
#pragma unroll
    for (int n = 0; n < 6; n++) {
        split3_pair(g_sC, r0 * 384 + cb + n * 8, of[n][0] * inv0, of[n][1] * inv0);
        split3_pair(g_sC, r1 * 384 + cb + n * 8, of[n][2] * inv1, of[n][3] * inv1);
    }
}

// ---------------- output projection + sigmoid --------------------------------
__global__ __launch_bounds__(256) void k_out(const float* __restrict__ Wout,
                                             const float* __restrict__ bout,
                                             float* __restrict__ out) {
    int warp = (blockIdx.x * blockDim.x + threadIdx.x) >> 5;
    int lane = threadIdx.x & 31;
    if (warp >= Nn) return;
    const float4* hr = (const float4*)(g_h + warp * Dd);
    const float4* wr = (const float4*)Wout;
    float s = 0.f;
#pragma unroll
    for (int q = 0; q < 3; q++) {
        float4 a = hr[lane + 32 * q];
        float4 b = wr[lane + 32 * q];
        s += a.x * b.x + a.y * b.y + a.z * b.z + a.w * b.w;
    }
#pragma unroll
    for (int off = 16; off; off >>= 1)
        s += __shfl_xor_sync(0xffffffffu, s, off);
    if (lane == 0) out[warp] = 1.f / (1.f + __expf(-(s + bout[0])));
}

// ---------------- launch ------------------------------------------------------
extern "C" void kernel_launch(void* const* d_in, const int* in_sizes, int n_in,
                              void* d_out, int out_size) {
    const float* emb  = (const float*)d_in[0];
    const int*   ei   = (const int*)d_in[1];
    const float* Wc   = (const float*)d_in[2];
    const float* bc   = (const float*)d_in[3];
    const float* Win  = (const float*)d_in[4];
    const float* bin  = (const float*)d_in[5];
    const float* Wao  = (const float*)d_in[6];
    const float* bao  = (const float*)d_in[7];
    const float* Wout = (const float*)d_in[8];
    const float* bout = (const float*)d_in[9];
    float* out = (float*)d_out;

    cudaFuncSetAttribute(k_flash_mma, cudaFuncAttributeMaxDynamicSharedMemorySize,
                         FL_SMEM);
    cudaFuncSetAttribute(k_gemm_mma<0>, cudaFuncAttributeMaxDynamicSharedMemorySize,
                         GM_SMEM);
    cudaFuncSetAttribute(k_gemm_mma<1>, cudaFuncAttributeMaxDynamicSharedMemorySize,
                         GM_SMEM);
    cudaFuncSetAttribute(k_gemm_mma<2>, cudaFuncAttributeMaxDynamicSharedMemorySize,
                         GM_SMEM);

    // CSR build + weight splits (reused across all 3 layers)
    k_zero_deg<<<Nn / 256, 256>>>();
    k_hist<<<Ee / 256, 256>>>(ei);
    k_scan<<<1, 1024>>>();
    k_fill<<<Ee / 256, 256>>>(ei);
    k_copy<<<(Nn * Dd / 4) / 256, 256>>>(emb);
    k_wsplit<<<432, 256>>>(Wc, 0, 3 * Dd * Dd / 4);
    k_wsplit<<<432, 256>>>(Win, OFF_WIN, 3 * Dd * Dd / 4);
    k_wsplit<<<144, 256>>>(Wao, OFF_WAO, Dd * Dd / 4);

    for (int l = 0; l < Ll; l++) {
        k_gather<<<Nn / 8, 256>>>();
        k_gemm_mma<0><<<dim3(Dd / 64, Nn / 128), 256, GM_SMEM>>>(OFF_CONV(l),
                                                                 bc + l * Dd);
        k_gemm_mma<1><<<dim3(3 * Dd / 64, Nn / 128), 256, GM_SMEM>>>(OFF_WIN, bin);
        k_flash_mma<<<dim3(Nn / 128, Hh), 256, FL_SMEM>>>();
        k_gemm_mma<2><<<dim3(Dd / 64, Nn / 128), 256, GM_SMEM>>>(OFF_WAO, bao);
    }
    k_out<<<Nn / 8, 256>>>(Wout, bout, out);
}

// round 13
// speedup vs baseline: 4.4754x; 1.2095x over previous
#include <cuda_runtime.h>
#include <cuda_bf16.h>
#include <math.h>
#include <stdint.h>

#define Nn 4096
#define Dd 384
#define Ee 131072
#define Hh 8
#define DHh 48
#define Ll 3
#define SEC (Hh * Nn * 48)

// ---------------- fast exp2 on the FMA pipe ----------------------------------
__device__ __forceinline__ float fexp2(float t) {
    t = fmaxf(t, -126.0f);
    float r = t + 12582912.0f;
    int n = __float_as_int(r) - 0x4B400000;
    float f = t - (r - 12582912.0f);
    float p = 1.8775767e-3f;
    p = fmaf(p, f, 8.9893397e-3f);
    p = fmaf(p, f, 5.5826318e-2f);
    p = fmaf(p, f, 2.4015361e-1f);
    p = fmaf(p, f, 6.9315308e-1f);
    p = fmaf(p, f, 1.0f);
    return __int_as_float(__float_as_int(p) + (n << 23));
}

// pack two fp32 -> bf16x2 word (low half = f0)
__device__ __forceinline__ uint32_t bf2(float f0, float f1) {
    uint32_t w;
    asm("cvt.rn.bf16x2.f32 %0, %1, %2;" : "=r"(w) : "f"(f1), "f"(f0));
    return w;
}
__device__ __forceinline__ float lof(uint32_t w) { return __uint_as_float(w << 16); }
__device__ __forceinline__ float hif(uint32_t w) { return __uint_as_float(w & 0xFFFF0000u); }

__device__ __forceinline__ uint32_t s2u(const void* p) {
    return (uint32_t)__cvta_generic_to_shared(p);
}
__device__ __forceinline__ void ldmx4(uint32_t r[4], uint32_t a) {
    asm volatile("ldmatrix.sync.aligned.m8n8.x4.shared.b16 {%0,%1,%2,%3}, [%4];"
                 : "=r"(r[0]), "=r"(r[1]), "=r"(r[2]), "=r"(r[3]) : "r"(a));
}
__device__ __forceinline__ void ldmx4t(uint32_t r[4], uint32_t a) {
    asm volatile("ldmatrix.sync.aligned.m8n8.x4.trans.shared.b16 {%0,%1,%2,%3}, [%4];"
                 : "=r"(r[0]), "=r"(r[1]), "=r"(r[2]), "=r"(r[3]) : "r"(a));
}
__device__ __forceinline__ void mma_bf16(float d[4], const uint32_t a[4],
                                         uint32_t b0, uint32_t b1) {
    asm volatile("mma.sync.aligned.m16n8k16.row.col.f32.bf16.bf16.f32 "
                 "{%0,%1,%2,%3}, {%4,%5,%6,%7}, {%8,%9}, {%0,%1,%2,%3};"
                 : "+f"(d[0]), "+f"(d[1]), "+f"(d[2]), "+f"(d[3])
                 : "r"(a[0]), "r"(a[1]), "r"(a[2]), "r"(a[3]), "r"(b0), "r"(b1));
}
__device__ __forceinline__ void cpasync16(uint32_t dst, const void* src) {
    asm volatile("cp.async.cg.shared.global [%0], [%1], 16;" :: "r"(dst), "l"(src));
}

// ---------------- scratch ----------------------------------------------------
__device__ __align__(16) float g_h[Nn * Dd];
__device__ int   g_deg[Nn];
__device__ float g_degf[Nn];
__device__ int   g_rowptr[Nn + 1];
__device__ int   g_fillpos[Nn];
__device__ int   g_colidx[Ee];
// bf16 split-3 activation buffers, layout [plane][node*384+col]
__device__ __align__(16) unsigned short g_sA[3][Nn * Dd];  // gather out (agg)
__device__ __align__(16) unsigned short g_sB[3][Nn * Dd];  // conv out  (hnew)
__device__ __align__(16) unsigned short g_sC[3][Nn * Dd];  // flash out (o)
// bf16 split-3 weights
#define WTOT 1032192
#define OFF_CONV(l) ((l) * Dd * Dd)
#define OFF_WIN (3 * Dd * Dd)
#define OFF_WAO (3 * Dd * Dd + 3 * Dd * Dd)
__device__ __align__(16) unsigned short g_ws[3][WTOT];
// flash-side Q/K/V split tensors: [arr][head][node][48]
__device__ __align__(16) unsigned short g_qs[3 * SEC];   // Q hi/mid/lo
__device__ __align__(16) unsigned short g_kvs[5 * SEC];  // K hi/mid/lo, V hi/lo

// split (v0,v1) into 3 bf16x2 planes of a [3][...] array
template <typename PT>
__device__ __forceinline__ void split3_pair(PT planes, int idx, float v0, float v1) {
    uint32_t w0 = bf2(v0, v1);
    *(uint32_t*)&planes[0][idx] = w0;
    float r0 = v0 - lof(w0), r1 = v1 - hif(w0);
    uint32_t w1 = bf2(r0, r1);
    *(uint32_t*)&planes[1][idx] = w1;
    *(uint32_t*)&planes[2][idx] = bf2(r0 - lof(w1), r1 - hif(w1));
}
// strided variants (base + plane*stride)
__device__ __forceinline__ void split3s(unsigned short* base, int stride, int idx,
                                        float v0, float v1) {
    uint32_t w0 = bf2(v0, v1);
    *(uint32_t*)&base[idx] = w0;
    float r0 = v0 - lof(w0), r1 = v1 - hif(w0);
    uint32_t w1 = bf2(r0, r1);
    *(uint32_t*)&base[stride + idx] = w1;
    *(uint32_t*)&base[2 * stride + idx] = bf2(r0 - lof(w1), r1 - hif(w1));
}
__device__ __forceinline__ void split2s(unsigned short* base, int stride, int idx,
                                        float v0, float v1) {
    uint32_t w0 = bf2(v0, v1);
    *(uint32_t*)&base[idx] = w0;
    *(uint32_t*)&base[stride + idx] = bf2(v0 - lof(w0), v1 - hif(w0));
}

// ---------------- CSR build --------------------------------------------------
__global__ void k_zero_deg() {
    int i = blockIdx.x * blockDim.x + threadIdx.x;
    if (i < Nn) g_deg[i] = 0;
}
__global__ void k_hist(const int* __restrict__ ei) {
    int e = blockIdx.x * blockDim.x + threadIdx.x;
    if (e < Ee) atomicAdd(&g_deg[ei[e]], 1);
}
__global__ void k_scan() {
    __shared__ int s[1024];
    int tid = threadIdx.x;
    int b = tid * 4;
    int v0 = g_deg[b], v1 = g_deg[b + 1], v2 = g_deg[b + 2], v3 = g_deg[b + 3];
    int p1 = v0 + v1, p2 = p1 + v2, p3 = p2 + v3;
    s[tid] = p3;
    __syncthreads();
    for (int off = 1; off < 1024; off <<= 1) {
        int t = (tid >= off) ? s[tid - off] : 0;
        __syncthreads();
        if (tid >= off) s[tid] += t;
        __syncthreads();
    }
    int prev = tid ? s[tid - 1] : 0;
    int e0 = prev, e1 = prev + v0, e2 = prev + p1, e3 = prev + p2;
    g_rowptr[b] = e0; g_rowptr[b + 1] = e1; g_rowptr[b + 2] = e2; g_rowptr[b + 3] = e3;
    g_fillpos[b] = e0; g_fillpos[b + 1] = e1; g_fillpos[b + 2] = e2; g_fillpos[b + 3] = e3;
    g_degf[b] = (float)v0; g_degf[b + 1] = (float)v1;
    g_degf[b + 2] = (float)v2; g_degf[b + 3] = (float)v3;
    if (tid == 1023) g_rowptr[Nn] = s[1023];
}
__global__ void k_fill(const int* __restrict__ ei) {
    int e = blockIdx.x * blockDim.x + threadIdx.x;
    if (e < Ee) {
        int dst = ei[e];
        int src = ei[Ee + e];
        int pos = atomicAdd(&g_fillpos[dst], 1);
        g_colidx[pos] = src;
    }
}
__global__ void k_copy(const float* __restrict__ emb) {
    int i = blockIdx.x * blockDim.x + threadIdx.x;
    if (i < Nn * Dd / 4)
        ((float4*)g_h)[i] = ((const float4*)emb)[i];
}

// ---------------- weight split (once per launch) ------------------------------
__global__ __launch_bounds__(256) void k_wsplit(const float* __restrict__ src,
                                                int dstoff, int n4) {
    int i = blockIdx.x * 256 + threadIdx.x;
    if (i >= n4) return;
    float4 x = ((const float4*)src)[i];
    int idx = dstoff + i * 4;
    split3_pair(g_ws, idx, x.x, x.y);
    split3_pair(g_ws, idx + 2, x.z, x.w);
}

// ---------------- neighbor aggregation -> split-3 bf16 ------------------------
__global__ __launch_bounds__(256) void k_gather() {
    int warp = (blockIdx.x * blockDim.x + threadIdx.x) >> 5;
    int lane = threadIdx.x & 31;
    if (warp >= Nn) return;
    int pbeg = g_rowptr[warp], pend = g_rowptr[warp + 1];
    float4 a0 = {0, 0, 0, 0}, a1 = a0, a2 = a0;
    for (int p = pbeg; p < pend; p++) {
        int src = g_colidx[p];
        const float4* r = (const float4*)(g_h + src * Dd);
        float4 x;
        x = r[lane];      a0.x += x.x; a0.y += x.y; a0.z += x.z; a0.w += x.w;
        x = r[lane + 32]; a1.x += x.x; a1.y += x.y; a1.z += x.z; a1.w += x.w;
        x = r[lane + 64]; a2.x += x.x; a2.y += x.y; a2.z += x.z; a2.w += x.w;
    }
    int base = warp * Dd + lane * 4;
    split3_pair(g_sA, base, a0.x, a0.y);
    split3_pair(g_sA, base + 2, a0.z, a0.w);
    split3_pair(g_sA, base + 128, a1.x, a1.y);
    split3_pair(g_sA, base + 130, a1.z, a1.w);
    split3_pair(g_sA, base + 256, a2.x, a2.y);
    split3_pair(g_sA, base + 258, a2.z, a2.w);
}

// ---------------- pipelined mma.sync GEMM: C = A * B^T + epilogue -------------
// 32-col k-chunks, double-buffered via cp.async (2 x 36 KB). 64B smem rows,
// swizzle (ch ^ ((row>>1)&3))*16 — conflict-free for both cp.async and ldmatrix.
// MODE 0: A=g_sA -> split-3 g_sB, bias*degf               (conv)
// MODE 1: A=g_sB -> split q/k/v directly into g_qs/g_kvs  (qkv + fused split)
// MODE 2: A=g_sC -> fp32 g_h, bias+residual+relu          (attn out)
#define GM_BUF 36864
#define GM_SMEM 73728

template <int MODE>
__global__ __launch_bounds__(256, 2) void k_gemm_mma(int woff,
                                                     const float* __restrict__ bias) {
    extern __shared__ __align__(128) char sm[];
    uint32_t smb = s2u(sm);
    const int tid = threadIdx.x, lane = tid & 31, w = tid >> 5;
    const int row0 = blockIdx.y * 128, col0 = blockIdx.x * 64;
    const int l15 = lane & 15, l7 = lane & 7;
    const int lhi = lane >> 4, lmid = (lane >> 3) & 1;

    float of[8][4];
#pragma unroll
    for (int i = 0; i < 8; i++)
#pragma unroll
        for (int j = 0; j < 4; j++) of[i][j] = 0.f;

    auto stage = [&](int kc, int buf) {
        uint32_t bb = smb + buf * GM_BUF;
        // A: 3 planes x 128 rows x 4 chunks(16B)
        for (int i = tid; i < 1536; i += 256) {
            int arr = i >> 9, rem = i & 511;
            int row = rem >> 2, ch = rem & 3;
            const unsigned short* ap = (MODE == 0) ? g_sA[arr]
                                     : (MODE == 1) ? g_sB[arr] : g_sC[arr];
            cpasync16(bb + arr * 8192 + row * 64 + ((ch ^ ((row >> 1) & 3)) * 16),
                      ap + (row0 + row) * 384 + kc * 32 + ch * 8);
        }
        // B: 3 planes x 64 rows x 4 chunks
        for (int i = tid; i < 768; i += 256) {
            int arr = i >> 8, rem = i & 255;
            int n = rem >> 2, ch = rem & 3;
            cpasync16(bb + 24576 + arr * 4096 + n * 64 + ((ch ^ ((n >> 1) & 3)) * 16),
                      g_ws[arr] + woff + (col0 + n) * 384 + kc * 32 + ch * 8);
        }
        asm volatile("cp.async.commit_group;" ::: "memory");
    };

    stage(0, 0);
    for (int kc = 0; kc < 12; kc++) {
        int buf = kc & 1;
        if (kc + 1 < 12) stage(kc + 1, buf ^ 1);
        else asm volatile("cp.async.commit_group;" ::: "memory");
        asm volatile("cp.async.wait_group 1;" ::: "memory");
        __syncthreads();

        uint32_t bb = smb + buf * GM_BUF;
#pragma unroll
        for (int asp = 0; asp < 3; asp++) {
            uint32_t Af[2][4];
#pragma unroll
            for (int kst = 0; kst < 2; kst++) {
                int row = 16 * w + l15, ch = 2 * kst + lhi;
                ldmx4(Af[kst], bb + asp * 8192 + row * 64 +
                               ((ch ^ ((row >> 1) & 3)) * 16));
            }
#pragma unroll
            for (int bsp = 0; bsp < 3; bsp++) {
                if (bsp <= 2 - asp) {
#pragma unroll
                    for (int kst = 0; kst < 2; kst++) {
#pragma unroll
                        for (int np = 0; np < 4; np++) {
                            int key = 8 * (2 * np + lhi) + l7, ch = 2 * kst + lmid;
                            uint32_t r[4];
                            ldmx4(r, bb + 24576 + bsp * 4096 + key * 64 +
                                     ((ch ^ ((key >> 1) & 3)) * 16));
                            mma_bf16(of[2 * np], Af[kst], r[0], r[1]);
                            mma_bf16(of[2 * np + 1], Af[kst], r[2], r[3]);
                        }
                    }
                }
            }
        }
        __syncthreads();
    }

    // epilogue
    const float qscale = 0.14433756729740643f * 1.4426950408889634f;
    int r0 = row0 + 16 * w + (lane >> 2), r1 = r0 + 8;
    int cbl = (lane & 3) * 2;
    float dg0 = (MODE == 0) ? g_degf[r0] : 1.f;
    float dg1 = (MODE == 0) ? g_degf[r1] : 1.f;
#pragma unroll
    for (int nt = 0; nt < 8; nt++) {
        int n = col0 + nt * 8 + cbl;
        float b0 = bias[n], b1 = bias[n + 1];
        float v00 = of[nt][0] + b0 * dg0, v01 = of[nt][1] + b1 * dg0;
        float v10 = of[nt][2] + b0 * dg1, v11 = of[nt][3] + b1 * dg1;
        if (MODE == 0) {
            split3_pair(g_sB, r0 * 384 + n, v00, v01);
            split3_pair(g_sB, r1 * 384 + n, v10, v11);
        } else if (MODE == 1) {
            int sec = n / 384;
            int wn = n - sec * 384;
            int hd = wn / 48, d = wn - hd * 48;
            int i0 = (hd * Nn + r0) * 48 + d;
            int i1 = (hd * Nn + r1) * 48 + d;
            if (sec == 0) {
                split3s(g_qs, SEC, i0, v00 * qscale, v01 * qscale);
                split3s(g_qs, SEC, i1, v10 * qscale, v11 * qscale);
            } else if (sec == 1) {
                split3s(g_kvs, SEC, i0, v00, v01);
                split3s(g_kvs, SEC, i1, v10, v11);
            } else {
                split2s(g_kvs + 3 * SEC, SEC, i0, v00, v01);
                split2s(g_kvs + 3 * SEC, SEC, i1, v10, v11);
            }
        } else {
            float2 h0 = *(const float2*)&g_h[r0 * 384 + n];
            float2 h1 = *(const float2*)&g_h[r1 * 384 + n];
            *(float2*)&g_h[r0 * 384 + n] =
                make_float2(fmaxf(v00 + h0.x, 0.f), fmaxf(v01 + h0.y, 0.f));
            *(float2*)&g_h[r1 * 384 + n] =
                make_float2(fmaxf(v10 + h1.x, 0.f), fmaxf(v11 + h1.y, 0.f));
        }
    }
}

// ---------------- mma.sync flash attention (pipelined) ------------------------
// Q A-fragments in registers (direct global loads); K/V double-buffered via
// cp.async. smem = 2 x 40960 B (K 3x8KB + V 2x8KB per buffer).
#define FL_SMEM 81920

__device__ __forceinline__ void flash_stage(uint32_t smb, int hN, int k0,
                                            int buf, int tid) {
    for (int i = tid; i < 1920; i += 256) {
        int arr = i / 384, rem = i - arr * 384;
        int row = rem / 6, c = rem - row * 6;
        const unsigned short* src = g_kvs + arr * SEC + (hN + k0 + row) * 48 + c * 8;
        uint32_t dst = smb + buf * 40960 + arr * 8192 + row * 128 +
                       ((c * 16) ^ ((row & 7) * 16));
        cpasync16(dst, src);
    }
    asm volatile("cp.async.commit_group;" ::: "memory");
}

__global__ __launch_bounds__(256, 2) void k_flash_mma() {
    extern __shared__ __align__(128) char sm[];
    uint32_t smb = s2u(sm);
    const int tid = threadIdx.x, lane = tid & 31, w = tid >> 5;
    const int head = blockIdx.y, q0 = blockIdx.x * 128;
    const int hN = head * Nn;
    const int l15 = lane & 15, l7 = lane & 7;
    const int lhi = lane >> 4, lmid = (lane >> 3) & 1;

    // Q A-fragments direct from global (row=16w+g(+8), col=16ks+2t(+8))
    uint32_t qf[3][3][4];
    {
        int rl = 16 * w + (lane >> 2);
        int cq = (lane & 3) * 2;
#pragma unroll
        for (int qs = 0; qs < 3; qs++) {
            const unsigned short* qp = g_qs + qs * SEC + (hN + q0) * 48;
#pragma unroll
            for (int ks = 0; ks < 3; ks++) {
                int c = 16 * ks + cq;
                qf[qs][ks][0] = *(const uint32_t*)&qp[rl * 48 + c];
                qf[qs][ks][1] = *(const uint32_t*)&qp[(rl + 8) * 48 + c];
                qf[qs][ks][2] = *(const uint32_t*)&qp[rl * 48 + c + 8];
                qf[qs][ks][3] = *(const uint32_t*)&qp[(rl + 8) * 48 + c + 8];
            }
        }
    }

    float of[6][4];
#pragma unroll
    for (int n = 0; n < 6; n++)
#pragma unroll
        for (int j = 0; j < 4; j++) of[n][j] = 0.f;
    float mr0 = -1e30f, mr1 = -1e30f, lr0 = 0.f, lr1 = 0.f;

    flash_stage(smb, hN, 0, 0, tid);   // prologue: tile 0 in flight

    for (int kt = 0; kt < 64; kt++) {
        int buf = kt & 1;
        uint32_t kvb = smb + buf * 40960;
        if (kt + 1 < 64)
            flash_stage(smb, hN, (kt + 1) * 64, buf ^ 1, tid);
        else
            asm volatile("cp.async.commit_group;" ::: "memory");
        asm volatile("cp.async.wait_group 1;" ::: "memory");
        __syncthreads();

        // ---- S = sum of 6 bf16 split terms ----
        float sf[8][4];
#pragma unroll
        for (int nt = 0; nt < 8; nt++)
#pragma unroll
            for (int j = 0; j < 4; j++) sf[nt][j] = 0.f;

#pragma unroll
        for (int ks = 0; ks < 3; ks++) {
#pragma unroll
            for (int kk = 0; kk < 3; kk++) {
                uint32_t Bf[8][2];
#pragma unroll
                for (int np = 0; np < 4; np++) {
                    int key = 8 * (2 * np + lhi) + l7;
                    int ch = 2 * ks + lmid;
                    uint32_t r[4];
                    ldmx4(r, kvb + kk * 8192 + key * 128 +
                             ((ch * 16) ^ ((key & 7) * 16)));
                    Bf[2 * np][0] = r[0]; Bf[2 * np][1] = r[1];
                    Bf[2 * np + 1][0] = r[2]; Bf[2 * np + 1][1] = r[3];
                }
#pragma unroll
                for (int qs = 0; qs < 3; qs++) {
                    if (qs + kk <= 2) {
#pragma unroll
                        for (int nt = 0; nt < 8; nt++)
                            mma_bf16(sf[nt], qf[qs][ks], Bf[nt][0], Bf[nt][1]);
                    }
                }
            }
        }

        // ---- online softmax (base-2) ----
        float vmax0 = -1e30f, vmax1 = -1e30f;
#pragma unroll
        for (int nt = 0; nt < 8; nt++) {
            vmax0 = fmaxf(vmax0, fmaxf(sf[nt][0], sf[nt][1]));
            vmax1 = fmaxf(vmax1, fmaxf(sf[nt][2], sf[nt][3]));
        }
        vmax0 = fmaxf(vmax0, __shfl_xor_sync(0xffffffffu, vmax0, 1));
        vmax0 = fmaxf(vmax0, __shfl_xor_sync(0xffffffffu, vmax0, 2));
        vmax1 = fmaxf(vmax1, __shfl_xor_sync(0xffffffffu, vmax1, 1));
        vmax1 = fmaxf(vmax1, __shfl_xor_sync(0xffffffffu, vmax1, 2));
        float nm0 = fmaxf(mr0, vmax0), nm1 = fmaxf(mr1, vmax1);
        float al0 = fexp2(mr0 - nm0), al1 = fexp2(mr1 - nm1);
        mr0 = nm0; mr1 = nm1;

        uint32_t pA[4][4];
        float ps0 = 0.f, ps1 = 0.f;
#pragma unroll
        for (int t = 0; t < 4; t++) {
            float p00 = fexp2(sf[2 * t][0] - nm0), p01 = fexp2(sf[2 * t][1] - nm0);
            float p10 = fexp2(sf[2 * t][2] - nm1), p11 = fexp2(sf[2 * t][3] - nm1);
            float p20 = fexp2(sf[2 * t + 1][0] - nm0), p21 = fexp2(sf[2 * t + 1][1] - nm0);
            float p30 = fexp2(sf[2 * t + 1][2] - nm1), p31 = fexp2(sf[2 * t + 1][3] - nm1);
            uint32_t w0 = bf2(p00, p01), w1 = bf2(p10, p11);
            uint32_t w2 = bf2(p20, p21), w3 = bf2(p30, p31);
            pA[t][0] = w0; pA[t][1] = w1; pA[t][2] = w2; pA[t][3] = w3;
            ps0 += lof(w0) + hif(w0) + lof(w2) + hif(w2);
            ps1 += lof(w1) + hif(w1) + lof(w3) + hif(w3);
        }
        ps0 += __shfl_xor_sync(0xffffffffu, ps0, 1);
        ps0 += __shfl_xor_sync(0xffffffffu, ps0, 2);
        ps1 += __shfl_xor_sync(0xffffffffu, ps1, 1);
        ps1 += __shfl_xor_sync(0xffffffffu, ps1, 2);
        lr0 = lr0 * al0 + ps0;
        lr1 = lr1 * al1 + ps1;
#pragma unroll
        for (int n = 0; n < 6; n++) {
            of[n][0] *= al0; of[n][1] *= al0;
            of[n][2] *= al1; of[n][3] *= al1;
        }

        // ---- O += P V ----
#pragma unroll
        for (int t = 0; t < 4; t++) {
#pragma unroll
            for (int vs = 0; vs < 2; vs++) {
#pragma unroll
                for (int np = 0; np < 3; np++) {
                    int key = 16 * t + l15;
                    int ch = 2 * np + lhi;
                    uint32_t r[4];
                    ldmx4t(r, kvb + 24576 + vs * 8192 + key * 128 +
                              ((ch * 16) ^ ((key & 7) * 16)));
                    mma_bf16(of[2 * np], pA[t], r[0], r[1]);
                    mma_bf16(of[2 * np + 1], pA[t], r[2], r[3]);
                }
            }
        }
        __syncthreads();
    }

    // ---- epilogue: normalize + split-3 store to g_sC ----
    float inv0 = 1.f / lr0, inv1 = 1.f / lr1;
    int r0 = q0 + 16 * w + (lane >> 2), r1 = r0 + 8;
    int cb = head * 48 + (lane & 3) * 2;
#pragma unroll
    for (int n = 0; n < 6; n++) {
        split3_pair(g_sC, r0 * 384 + cb + n * 8, of[n][0] * inv0, of[n][1] * inv0);
        split3_pair(g_sC, r1 * 384 + cb + n * 8, of[n][2] * inv1, of[n][3] * inv1);
    }
}

// ---------------- output projection + sigmoid --------------------------------
__global__ __launch_bounds__(256) void k_out(const float* __restrict__ Wout,
                                             const float* __restrict__ bout,
                                             float* __restrict__ out) {
    int warp = (blockIdx.x * blockDim.x + threadIdx.x) >> 5;
    int lane = threadIdx.x & 31;
    if (warp >= Nn) return;
    const float4* hr = (const float4*)(g_h + warp * Dd);
    const float4* wr = (const float4*)Wout;
    float s = 0.f;
#pragma unroll
    for (int q = 0; q < 3; q++) {
        float4 a = hr[lane + 32 * q];
        float4 b = wr[lane + 32 * q];
        s += a.x * b.x + a.y * b.y + a.z * b.z + a.w * b.w;
    }
#pragma unroll
    for (int off = 16; off; off >>= 1)
        s += __shfl_xor_sync(0xffffffffu, s, off);
    if (lane == 0) out[warp] = 1.f / (1.f + __expf(-(s + bout[0])));
}

// ---------------- launch ------------------------------------------------------
extern "C" void kernel_launch(void* const* d_in, const int* in_sizes, int n_in,
                              void* d_out, int out_size) {
    const float* emb  = (const float*)d_in[0];
    const int*   ei   = (const int*)d_in[1];
    const float* Wc   = (const float*)d_in[2];
    const float* bc   = (const float*)d_in[3];
    const float* Win  = (const float*)d_in[4];
    const float* bin  = (const float*)d_in[5];
    const float* Wao  = (const float*)d_in[6];
    const float* bao  = (const float*)d_in[7];
    const float* Wout = (const float*)d_in[8];
    const float* bout = (const float*)d_in[9];
    float* out = (float*)d_out;

    cudaFuncSetAttribute(k_flash_mma, cudaFuncAttributeMaxDynamicSharedMemorySize,
                         FL_SMEM);
    cudaFuncSetAttribute(k_gemm_mma<0>, cudaFuncAttributeMaxDynamicSharedMemorySize,
                         GM_SMEM);
    cudaFuncSetAttribute(k_gemm_mma<1>, cudaFuncAttributeMaxDynamicSharedMemorySize,
                         GM_SMEM);
    cudaFuncSetAttribute(k_gemm_mma<2>, cudaFuncAttributeMaxDynamicSharedMemorySize,
                         GM_SMEM);

    // CSR build + weight splits (reused across all 3 layers)
    k_zero_deg<<<Nn / 256, 256>>>();
    k_hist<<<Ee / 256, 256>>>(ei);
    k_scan<<<1, 1024>>>();
    k_fill<<<Ee / 256, 256>>>(ei);
    k_copy<<<(Nn * Dd / 4) / 256, 256>>>(emb);
    k_wsplit<<<432, 256>>>(Wc, 0, 3 * Dd * Dd / 4);
    k_wsplit<<<432, 256>>>(Win, OFF_WIN, 3 * Dd * Dd / 4);
    k_wsplit<<<144, 256>>>(Wao, OFF_WAO, Dd * Dd / 4);

    for (int l = 0; l < Ll; l++) {
        k_gather<<<Nn / 8, 256>>>();
        k_gemm_mma<0><<<dim3(Dd / 64, Nn / 128), 256, GM_SMEM>>>(OFF_CONV(l),
                                                                 bc + l * Dd);
        k_gemm_mma<1><<<dim3(3 * Dd / 64, Nn / 128), 256, GM_SMEM>>>(OFF_WIN, bin);
        k_flash_mma<<<dim3(Nn / 128, Hh), 256, FL_SMEM>>>();
        k_gemm_mma<2><<<dim3(Dd / 64, Nn / 128), 256, GM_SMEM>>>(OFF_WAO, bao);
    }
    k_out<<<Nn / 8, 256>>>(Wout, bout, out);
}